// round 1
// baseline (speedup 1.0000x reference)
#include <cuda_runtime.h>
#include <math.h>

#define SEQ 2048
#define BAT 4
#define EMB 512
#define NH  8
#define HD  64
#define FFD 2048
#define WIN 128
#define TOK (SEQ*BAT)            // 8192
#define QKVE (3*EMB)             // 1536

// ---------------- scratch (device globals; no allocation) ----------------
__device__ float g_xp[TOK*EMB];      // x + pos (residual source 1)
__device__ float g_qkv[TOK*QKVE];    // qkv projection
__device__ float g_y[TOK*EMB];       // attention output (pre out-proj)
__device__ float g_tmp[TOK*EMB];     // attn_out, later ff_out
__device__ float g_ln1[TOK*EMB];     // after first LN (residual source 2)
__device__ float g_ffh[TOK*FFD];     // ff hidden

// ---------------- kernel 1: x + pos (broadcast quirk: pos[0, b, :]) ------
__global__ void add_pos_kernel(const float* __restrict__ x,
                               const float* __restrict__ pos)
{
    int idx = blockIdx.x * 256 + threadIdx.x;   // TOK*EMB = 4M
    int e = idx & (EMB - 1);
    int b = (idx >> 9) & (BAT - 1);             // token index / EMB, % BAT
    g_xp[idx] = x[idx] + pos[b * EMB + e];
}

// ---------------- generic GEMM: C[M,N] = A[M,K] @ Bw[N,K]^T + bias -------
#define BM 64
#define BN 64
#define BK 16
__global__ void gemm_kernel(const float* __restrict__ A,
                            const float* __restrict__ Bw,
                            const float* __restrict__ bias,
                            float* __restrict__ C,
                            int M, int N, int K, int relu)
{
    __shared__ float As[BM][BK + 1];
    __shared__ float Bs[BN][BK + 1];
    const int tx = threadIdx.x & 15;
    const int ty = threadIdx.x >> 4;
    const int m0 = blockIdx.y * BM;
    const int n0 = blockIdx.x * BN;

    float acc[4][4] = {};
    for (int k0 = 0; k0 < K; k0 += BK) {
        #pragma unroll
        for (int u = 0; u < 4; u++) {
            int idx = threadIdx.x + u * 256;
            int r = idx >> 4, c = idx & 15;
            As[r][c] = A[(size_t)(m0 + r) * K + k0 + c];
            Bs[r][c] = Bw[(size_t)(n0 + r) * K + k0 + c];
        }
        __syncthreads();
        #pragma unroll
        for (int kk = 0; kk < BK; kk++) {
            float a[4], bb[4];
            #pragma unroll
            for (int r = 0; r < 4; r++) a[r]  = As[ty * 4 + r][kk];
            #pragma unroll
            for (int c = 0; c < 4; c++) bb[c] = Bs[tx * 4 + c][kk];
            #pragma unroll
            for (int r = 0; r < 4; r++)
                #pragma unroll
                for (int c = 0; c < 4; c++)
                    acc[r][c] += a[r] * bb[c];
        }
        __syncthreads();
    }
    #pragma unroll
    for (int r = 0; r < 4; r++) {
        int m = m0 + ty * 4 + r;
        #pragma unroll
        for (int c = 0; c < 4; c++) {
            int n = n0 + tx * 4 + c;
            float v = acc[r][c] + bias[n];
            if (relu) v = fmaxf(v, 0.0f);
            C[(size_t)m * N + n] = v;
        }
    }
}

// ---------------- sparse local+global attention ---------------------------
// One 128-thread block per (query row i, batch b, head h).
// Allowed cols: |i-j| <= WIN  OR  j % (2*WIN) == 0.  (<= 257 + 8 entries)
__global__ void attn_kernel()
{
    const int i   = blockIdx.x;
    const int b   = blockIdx.y >> 3;   // NH = 8
    const int h   = blockIdx.y & 7;
    const int tid = threadIdx.x;

    __shared__ __align__(16) float qs[HD];
    __shared__ float sc[272];
    __shared__ int   jl[272];
    __shared__ int   s_cnt;
    __shared__ float red[4];
    __shared__ float s_stat[2];        // max, sum
    __shared__ float ypart[2][HD];

    int jlo = i - WIN; if (jlo < 0) jlo = 0;
    int jhi = i + WIN; if (jhi > SEQ - 1) jhi = SEQ - 1;
    const int nwin = jhi - jlo + 1;

    for (int t = tid; t < nwin; t += 128) jl[t] = jlo + t;
    if (tid == 0) {
        int c = nwin;
        for (int g = 0; g < SEQ; g += 2 * WIN)
            if (g < jlo || g > jhi) jl[c++] = g;
        s_cnt = c;
    }
    if (tid < HD)
        qs[tid] = g_qkv[((size_t)i * BAT + b) * QKVE + h * HD + tid] * 0.125f;
    __syncthreads();
    const int cnt = s_cnt;

    // --- scores (q.k) ---
    float lmax = -1e30f;
    for (int t = tid; t < cnt; t += 128) {
        const int j = jl[t];
        const float4* kp = (const float4*)(g_qkv + ((size_t)j * BAT + b) * QKVE + EMB + h * HD);
        const float4* qp = (const float4*)qs;
        float d = 0.0f;
        #pragma unroll
        for (int u = 0; u < HD / 4; u++) {
            float4 kv = kp[u], qv = qp[u];
            d += qv.x * kv.x + qv.y * kv.y + qv.z * kv.z + qv.w * kv.w;
        }
        sc[t] = d;
        lmax = fmaxf(lmax, d);
    }
    // block max
    #pragma unroll
    for (int o = 16; o; o >>= 1) lmax = fmaxf(lmax, __shfl_xor_sync(~0u, lmax, o));
    if ((tid & 31) == 0) red[tid >> 5] = lmax;
    __syncthreads();
    const float mx = fmaxf(fmaxf(red[0], red[1]), fmaxf(red[2], red[3]));
    __syncthreads();

    // --- exp & sum ---
    float lsum = 0.0f;
    for (int t = tid; t < cnt; t += 128) {
        float p = __expf(sc[t] - mx);
        sc[t] = p;
        lsum += p;
    }
    #pragma unroll
    for (int o = 16; o; o >>= 1) lsum += __shfl_xor_sync(~0u, lsum, o);
    if ((tid & 31) == 0) red[tid >> 5] = lsum;
    __syncthreads();
    if (tid == 0) s_stat[0] = red[0] + red[1] + red[2] + red[3];
    __syncthreads();
    const float inv_sum = 1.0f / s_stat[0];

    // --- y[d] = sum_j p_j * v[j, d] ---
    const int d    = tid & 63;
    const int half = tid >> 6;
    float acc = 0.0f;
    for (int t = half; t < cnt; t += 2) {
        const int j = jl[t];
        acc += sc[t] * g_qkv[((size_t)j * BAT + b) * QKVE + 2 * EMB + h * HD + d];
    }
    ypart[half][d] = acc;
    __syncthreads();
    if (tid < HD)
        g_y[((size_t)i * BAT + b) * EMB + h * HD + tid] =
            (ypart[0][tid] + ypart[1][tid]) * inv_sum;
}

// ---------------- fused residual add + layernorm --------------------------
__global__ void add_ln_kernel(const float* __restrict__ a,
                              const float* __restrict__ r,
                              const float* __restrict__ g,
                              const float* __restrict__ be,
                              float* __restrict__ out)
{
    const int row = blockIdx.x;       // token
    const int tid = threadIdx.x;      // 128 threads, 4 elems each
    __shared__ float red[4];
    __shared__ float s_stat[2];

    float v[4];
    float s = 0.0f;
    #pragma unroll
    for (int u = 0; u < 4; u++) {
        int e = tid + u * 128;
        v[u] = a[(size_t)row * EMB + e] + r[(size_t)row * EMB + e];
        s += v[u];
    }
    #pragma unroll
    for (int o = 16; o; o >>= 1) s += __shfl_xor_sync(~0u, s, o);
    if ((tid & 31) == 0) red[tid >> 5] = s;
    __syncthreads();
    const float mean = (red[0] + red[1] + red[2] + red[3]) * (1.0f / EMB);
    __syncthreads();

    float s2 = 0.0f;
    #pragma unroll
    for (int u = 0; u < 4; u++) {
        float dl = v[u] - mean;
        s2 += dl * dl;
    }
    #pragma unroll
    for (int o = 16; o; o >>= 1) s2 += __shfl_xor_sync(~0u, s2, o);
    if ((tid & 31) == 0) red[tid >> 5] = s2;
    __syncthreads();
    if (tid == 0) s_stat[0] = (red[0] + red[1] + red[2] + red[3]) * (1.0f / EMB);
    __syncthreads();
    const float rstd = rsqrtf(s_stat[0] + 1e-5f);

    #pragma unroll
    for (int u = 0; u < 4; u++) {
        int e = tid + u * 128;
        out[(size_t)row * EMB + e] = (v[u] - mean) * rstd * g[e] + be[e];
    }
}

// ---------------- launch ---------------------------------------------------
extern "C" void kernel_launch(void* const* d_in, const int* in_sizes, int n_in,
                              void* d_out, int out_size)
{
    const float* x         = (const float*)d_in[0];
    const float* pos       = (const float*)d_in[1];
    const float* in_proj_w = (const float*)d_in[2];
    const float* in_proj_b = (const float*)d_in[3];
    const float* out_w     = (const float*)d_in[4];
    const float* out_b     = (const float*)d_in[5];
    const float* w1        = (const float*)d_in[6];
    const float* b1        = (const float*)d_in[7];
    const float* w2        = (const float*)d_in[8];
    const float* b2        = (const float*)d_in[9];
    const float* g1        = (const float*)d_in[10];
    const float* be1       = (const float*)d_in[11];
    const float* g2        = (const float*)d_in[12];
    const float* be2       = (const float*)d_in[13];
    float* out = (float*)d_out;

    float *xp, *qkv, *y, *tmp, *ln1, *ffh;
    cudaGetSymbolAddress((void**)&xp,  g_xp);
    cudaGetSymbolAddress((void**)&qkv, g_qkv);
    cudaGetSymbolAddress((void**)&y,   g_y);
    cudaGetSymbolAddress((void**)&tmp, g_tmp);
    cudaGetSymbolAddress((void**)&ln1, g_ln1);
    cudaGetSymbolAddress((void**)&ffh, g_ffh);

    // 1. x + pos
    add_pos_kernel<<<(TOK * EMB) / 256, 256>>>(x, pos);

    // 2. QKV projection: (8192,512) @ (512,1536)
    gemm_kernel<<<dim3(QKVE / BN, TOK / BM), 256>>>(xp, in_proj_w, in_proj_b, qkv,
                                                    TOK, QKVE, EMB, 0);

    // 3. sparse attention
    attn_kernel<<<dim3(SEQ, BAT * NH), 128>>>();

    // 4. out projection
    gemm_kernel<<<dim3(EMB / BN, TOK / BM), 256>>>(y, out_w, out_b, tmp,
                                                   TOK, EMB, EMB, 0);

    // 5. residual + LN1
    add_ln_kernel<<<TOK, 128>>>(xp, tmp, g1, be1, ln1);

    // 6. FF1 + ReLU
    gemm_kernel<<<dim3(FFD / BN, TOK / BM), 256>>>(ln1, w1, b1, ffh,
                                                   TOK, FFD, EMB, 1);

    // 7. FF2
    gemm_kernel<<<dim3(EMB / BN, TOK / BM), 256>>>(ffh, w2, b2, tmp,
                                                   TOK, EMB, FFD, 0);

    // 8. residual + LN2 -> output
    add_ln_kernel<<<TOK, 128>>>(ln1, tmp, g2, be2, out);
}

// round 2
// speedup vs baseline: 1.7961x; 1.7961x over previous
#include <cuda_runtime.h>
#include <math.h>
#include <stdint.h>

#define SEQ 2048
#define BAT 4
#define EMB 512
#define NH  8
#define HD  64
#define FFD 2048
#define WIN 128
#define TOK (SEQ*BAT)            // 8192
#define QKVE (3*EMB)             // 1536

// ---------------- scratch (device globals; no allocation) ----------------
__device__ float g_xp[TOK*EMB];      // x + pos (residual source 1)
__device__ float g_qkv[TOK*QKVE];    // qkv projection
__device__ float g_y[TOK*EMB];       // attention output (pre out-proj)
__device__ float g_tmp[TOK*EMB];     // attn_out, later ff_out
__device__ float g_ln1[TOK*EMB];     // after first LN (residual source 2)
__device__ float g_ffh[TOK*FFD];     // ff hidden

// ---------------- kernel 1: x + pos (broadcast quirk: pos[0, b, :]) ------
__global__ void add_pos_kernel(const float* __restrict__ x,
                               const float* __restrict__ pos)
{
    int idx = blockIdx.x * 256 + threadIdx.x;      // over TOK*EMB/4 float4s
    int e4 = idx & (EMB / 4 - 1);
    int b  = (idx >> 7) & (BAT - 1);
    float4 xv = ((const float4*)x)[idx];
    float4 pv = ((const float4*)pos)[b * (EMB / 4) + e4];
    xv.x += pv.x; xv.y += pv.y; xv.z += pv.z; xv.w += pv.w;
    ((float4*)g_xp)[idx] = xv;
}

// ---------------- TF32 tensor-core GEMM -----------------------------------
// C[M,N] = A[M,K] @ Bw[N,K]^T + bias  (optional relu)
// 128x128 block tile, BK=16, 8 warps of 32x64 warp tiles, cp.async 2-stage.
#define LDS 20          // padded float stride for 16-float rows

__device__ __forceinline__ uint32_t f2tf(float x)
{
    uint32_t r;
    asm("cvt.rna.tf32.f32 %0, %1;" : "=r"(r) : "f"(x));
    return r;
}

__global__ void __launch_bounds__(256) gemm_tf32(
    const float* __restrict__ A, const float* __restrict__ Bw,
    const float* __restrict__ bias, float* __restrict__ C,
    int M, int N, int K, int relu)
{
    __shared__ float As[2][128 * LDS];
    __shared__ float Bs[2][128 * LDS];

    const int tid  = threadIdx.x;
    const int warp = tid >> 5, lane = tid & 31;
    const int wm = warp & 3, wn = warp >> 2;       // 4 x 2 warp grid
    const int l4 = lane >> 2, lq = lane & 3;
    const int m0 = blockIdx.y * 128, n0 = blockIdx.x * 128;

    float acc[2][8][4];
    #pragma unroll
    for (int a = 0; a < 2; a++)
        #pragma unroll
        for (int b = 0; b < 8; b++)
            #pragma unroll
            for (int c = 0; c < 4; c++) acc[a][b][c] = 0.0f;

    // async stage of one BK=16 tile (A:128x16, B:128x16) into buffer s
    #define STAGE(s, k0)                                                        \
    {                                                                           \
        _Pragma("unroll")                                                       \
        for (int u = 0; u < 2; u++) {                                           \
            int chunk = tid + u * 256;                                          \
            int row = chunk >> 2, c4 = chunk & 3;                               \
            const float* srcA = A + (size_t)(m0 + row) * K + (k0) + c4 * 4;     \
            uint32_t dstA = (uint32_t)__cvta_generic_to_shared(                 \
                                &As[s][row * LDS + c4 * 4]);                    \
            asm volatile("cp.async.cg.shared.global [%0], [%1], 16;"            \
                         :: "r"(dstA), "l"(srcA));                              \
            const float* srcB = Bw + (size_t)(n0 + row) * K + (k0) + c4 * 4;    \
            uint32_t dstB = (uint32_t)__cvta_generic_to_shared(                 \
                                &Bs[s][row * LDS + c4 * 4]);                    \
            asm volatile("cp.async.cg.shared.global [%0], [%1], 16;"            \
                         :: "r"(dstB), "l"(srcB));                              \
        }                                                                       \
        asm volatile("cp.async.commit_group;");                                 \
    }

    const int nk = K >> 4;
    STAGE(0, 0);
    for (int kt = 0; kt < nk; kt++) {
        if (kt + 1 < nk) {
            STAGE((kt + 1) & 1, (kt + 1) * 16);
            asm volatile("cp.async.wait_group 1;");
        } else {
            asm volatile("cp.async.wait_group 0;");
        }
        __syncthreads();
        const float* as = As[kt & 1];
        const float* bs = Bs[kt & 1];
        #pragma unroll
        for (int ks = 0; ks < 16; ks += 8) {
            uint32_t af[2][4], bf[8][2];
            #pragma unroll
            for (int mt = 0; mt < 2; mt++) {
                int rb = wm * 32 + mt * 16 + l4;
                af[mt][0] = f2tf(as[rb * LDS + ks + lq]);
                af[mt][1] = f2tf(as[(rb + 8) * LDS + ks + lq]);
                af[mt][2] = f2tf(as[rb * LDS + ks + lq + 4]);
                af[mt][3] = f2tf(as[(rb + 8) * LDS + ks + lq + 4]);
            }
            #pragma unroll
            for (int nt = 0; nt < 8; nt++) {
                int nb = wn * 64 + nt * 8 + l4;
                bf[nt][0] = f2tf(bs[nb * LDS + ks + lq]);
                bf[nt][1] = f2tf(bs[nb * LDS + ks + lq + 4]);
            }
            #pragma unroll
            for (int mt = 0; mt < 2; mt++)
                #pragma unroll
                for (int nt = 0; nt < 8; nt++) {
                    float* c = acc[mt][nt];
                    asm volatile(
                        "mma.sync.aligned.m16n8k8.row.col.f32.tf32.tf32.f32 "
                        "{%0,%1,%2,%3}, {%4,%5,%6,%7}, {%8,%9}, {%0,%1,%2,%3};"
                        : "+f"(c[0]), "+f"(c[1]), "+f"(c[2]), "+f"(c[3])
                        : "r"(af[mt][0]), "r"(af[mt][1]),
                          "r"(af[mt][2]), "r"(af[mt][3]),
                          "r"(bf[nt][0]), "r"(bf[nt][1]));
                }
        }
        __syncthreads();
    }

    // epilogue: bias (+relu), float2 stores
    #pragma unroll
    for (int mt = 0; mt < 2; mt++) {
        int row = m0 + wm * 32 + mt * 16 + l4;
        #pragma unroll
        for (int nt = 0; nt < 8; nt++) {
            int col = n0 + wn * 64 + nt * 8 + lq * 2;
            float b0 = bias[col], b1 = bias[col + 1];
            float v0 = acc[mt][nt][0] + b0, v1 = acc[mt][nt][1] + b1;
            float v2 = acc[mt][nt][2] + b0, v3 = acc[mt][nt][3] + b1;
            if (relu) {
                v0 = fmaxf(v0, 0.0f); v1 = fmaxf(v1, 0.0f);
                v2 = fmaxf(v2, 0.0f); v3 = fmaxf(v3, 0.0f);
            }
            *(float2*)&C[(size_t)row * N + col]       = make_float2(v0, v1);
            *(float2*)&C[(size_t)(row + 8) * N + col] = make_float2(v2, v3);
        }
    }
}

// ---------------- sparse local+global attention ---------------------------
// One 128-thread block per (query row i, batch b, head h).
// Allowed cols: |i-j| <= WIN  OR  j % (2*WIN) == 0.  (<= 257 + 8 entries)
__global__ void attn_kernel()
{
    const int i   = blockIdx.x;
    const int b   = blockIdx.y >> 3;   // NH = 8
    const int h   = blockIdx.y & 7;
    const int tid = threadIdx.x;

    __shared__ __align__(16) float qs[HD];
    __shared__ float sc[272];
    __shared__ int   jl[272];
    __shared__ int   s_cnt;
    __shared__ float red[4];
    __shared__ float s_stat[2];
    __shared__ float ypart[2][HD];

    int jlo = i - WIN; if (jlo < 0) jlo = 0;
    int jhi = i + WIN; if (jhi > SEQ - 1) jhi = SEQ - 1;
    const int nwin = jhi - jlo + 1;

    for (int t = tid; t < nwin; t += 128) jl[t] = jlo + t;
    if (tid == 0) {
        int c = nwin;
        for (int g = 0; g < SEQ; g += 2 * WIN)
            if (g < jlo || g > jhi) jl[c++] = g;
        s_cnt = c;
    }
    if (tid < HD)
        qs[tid] = g_qkv[((size_t)i * BAT + b) * QKVE + h * HD + tid] * 0.125f;
    __syncthreads();
    const int cnt = s_cnt;

    float lmax = -1e30f;
    for (int t = tid; t < cnt; t += 128) {
        const int j = jl[t];
        const float4* kp = (const float4*)(g_qkv + ((size_t)j * BAT + b) * QKVE + EMB + h * HD);
        const float4* qp = (const float4*)qs;
        float d = 0.0f;
        #pragma unroll
        for (int u = 0; u < HD / 4; u++) {
            float4 kv = kp[u], qv = qp[u];
            d += qv.x * kv.x + qv.y * kv.y + qv.z * kv.z + qv.w * kv.w;
        }
        sc[t] = d;
        lmax = fmaxf(lmax, d);
    }
    #pragma unroll
    for (int o = 16; o; o >>= 1) lmax = fmaxf(lmax, __shfl_xor_sync(~0u, lmax, o));
    if ((tid & 31) == 0) red[tid >> 5] = lmax;
    __syncthreads();
    const float mx = fmaxf(fmaxf(red[0], red[1]), fmaxf(red[2], red[3]));
    __syncthreads();

    float lsum = 0.0f;
    for (int t = tid; t < cnt; t += 128) {
        float p = __expf(sc[t] - mx);
        sc[t] = p;
        lsum += p;
    }
    #pragma unroll
    for (int o = 16; o; o >>= 1) lsum += __shfl_xor_sync(~0u, lsum, o);
    if ((tid & 31) == 0) red[tid >> 5] = lsum;
    __syncthreads();
    if (tid == 0) s_stat[0] = red[0] + red[1] + red[2] + red[3];
    __syncthreads();
    const float inv_sum = 1.0f / s_stat[0];

    const int d    = tid & 63;
    const int half = tid >> 6;
    float acc = 0.0f;
    for (int t = half; t < cnt; t += 2) {
        const int j = jl[t];
        acc += sc[t] * g_qkv[((size_t)j * BAT + b) * QKVE + 2 * EMB + h * HD + d];
    }
    ypart[half][d] = acc;
    __syncthreads();
    if (tid < HD)
        g_y[((size_t)i * BAT + b) * EMB + h * HD + tid] =
            (ypart[0][tid] + ypart[1][tid]) * inv_sum;
}

// ---------------- fused residual add + layernorm --------------------------
__global__ void add_ln_kernel(const float* __restrict__ a,
                              const float* __restrict__ r,
                              const float* __restrict__ g,
                              const float* __restrict__ be,
                              float* __restrict__ out)
{
    const int row = blockIdx.x;
    const int tid = threadIdx.x;
    __shared__ float red[4];
    __shared__ float s_stat[2];

    float v[4];
    float s = 0.0f;
    #pragma unroll
    for (int u = 0; u < 4; u++) {
        int e = tid + u * 128;
        v[u] = a[(size_t)row * EMB + e] + r[(size_t)row * EMB + e];
        s += v[u];
    }
    #pragma unroll
    for (int o = 16; o; o >>= 1) s += __shfl_xor_sync(~0u, s, o);
    if ((tid & 31) == 0) red[tid >> 5] = s;
    __syncthreads();
    const float mean = (red[0] + red[1] + red[2] + red[3]) * (1.0f / EMB);
    __syncthreads();

    float s2 = 0.0f;
    #pragma unroll
    for (int u = 0; u < 4; u++) {
        float dl = v[u] - mean;
        s2 += dl * dl;
    }
    #pragma unroll
    for (int o = 16; o; o >>= 1) s2 += __shfl_xor_sync(~0u, s2, o);
    if ((tid & 31) == 0) red[tid >> 5] = s2;
    __syncthreads();
    if (tid == 0) s_stat[0] = (red[0] + red[1] + red[2] + red[3]) * (1.0f / EMB);
    __syncthreads();
    const float rstd = rsqrtf(s_stat[0] + 1e-5f);

    #pragma unroll
    for (int u = 0; u < 4; u++) {
        int e = tid + u * 128;
        out[(size_t)row * EMB + e] = (v[u] - mean) * rstd * g[e] + be[e];
    }
}

// ---------------- launch ---------------------------------------------------
extern "C" void kernel_launch(void* const* d_in, const int* in_sizes, int n_in,
                              void* d_out, int out_size)
{
    const float* x         = (const float*)d_in[0];
    const float* pos       = (const float*)d_in[1];
    const float* in_proj_w = (const float*)d_in[2];
    const float* in_proj_b = (const float*)d_in[3];
    const float* out_w     = (const float*)d_in[4];
    const float* out_b     = (const float*)d_in[5];
    const float* w1        = (const float*)d_in[6];
    const float* b1        = (const float*)d_in[7];
    const float* w2        = (const float*)d_in[8];
    const float* b2        = (const float*)d_in[9];
    const float* g1        = (const float*)d_in[10];
    const float* be1       = (const float*)d_in[11];
    const float* g2        = (const float*)d_in[12];
    const float* be2       = (const float*)d_in[13];
    float* out = (float*)d_out;

    float *xp, *qkv, *y, *tmp, *ln1, *ffh;
    cudaGetSymbolAddress((void**)&xp,  g_xp);
    cudaGetSymbolAddress((void**)&qkv, g_qkv);
    cudaGetSymbolAddress((void**)&y,   g_y);
    cudaGetSymbolAddress((void**)&tmp, g_tmp);
    cudaGetSymbolAddress((void**)&ln1, g_ln1);
    cudaGetSymbolAddress((void**)&ffh, g_ffh);

    // 1. x + pos
    add_pos_kernel<<<(TOK * EMB / 4) / 256, 256>>>(x, pos);

    // 2. QKV projection: (8192,512) @ (512,1536)
    gemm_tf32<<<dim3(QKVE / 128, TOK / 128), 256>>>(xp, in_proj_w, in_proj_b, qkv,
                                                    TOK, QKVE, EMB, 0);

    // 3. sparse attention
    attn_kernel<<<dim3(SEQ, BAT * NH), 128>>>();

    // 4. out projection
    gemm_tf32<<<dim3(EMB / 128, TOK / 128), 256>>>(y, out_w, out_b, tmp,
                                                   TOK, EMB, EMB, 0);

    // 5. residual + LN1
    add_ln_kernel<<<TOK, 128>>>(xp, tmp, g1, be1, ln1);

    // 6. FF1 + ReLU
    gemm_tf32<<<dim3(FFD / 128, TOK / 128), 256>>>(ln1, w1, b1, ffh,
                                                   TOK, FFD, EMB, 1);

    // 7. FF2
    gemm_tf32<<<dim3(EMB / 128, TOK / 128), 256>>>(ffh, w2, b2, tmp,
                                                   TOK, EMB, FFD, 0);

    // 8. residual + LN2 -> output
    add_ln_kernel<<<TOK, 128>>>(ln1, tmp, g2, be2, out);
}

// round 3
// speedup vs baseline: 4.4026x; 2.4512x over previous
#include <cuda_runtime.h>
#include <math.h>
#include <stdint.h>

#define SEQ 2048
#define BAT 4
#define EMB 512
#define NH  8
#define HD  64
#define FFD 2048
#define WIN 128
#define TOK (SEQ*BAT)            // 8192
#define QKVE (3*EMB)             // 1536

// ---------------- scratch (device globals; no allocation) ----------------
__device__ float g_xp[TOK*EMB];      // x + pos (residual source 1)
__device__ float g_qkv[TOK*QKVE];    // qkv projection
__device__ float g_y[TOK*EMB];       // attention output (pre out-proj)
__device__ float g_tmp[TOK*EMB];     // attn_out, later ff_out
__device__ float g_ln1[TOK*EMB];     // after first LN (residual source 2)
__device__ float g_ffh[TOK*FFD];     // ff hidden

// ---------------- kernel 1: x + pos (broadcast quirk: pos[0, b, :]) ------
__global__ void add_pos_kernel(const float* __restrict__ x,
                               const float* __restrict__ pos)
{
    int idx = blockIdx.x * 256 + threadIdx.x;      // over TOK*EMB/4 float4s
    int e4 = idx & (EMB / 4 - 1);
    int b  = (idx >> 7) & (BAT - 1);
    float4 xv = ((const float4*)x)[idx];
    float4 pv = ((const float4*)pos)[b * (EMB / 4) + e4];
    xv.x += pv.x; xv.y += pv.y; xv.z += pv.z; xv.w += pv.w;
    ((float4*)g_xp)[idx] = xv;
}

// ---------------- TF32 tensor-core GEMM -----------------------------------
// C[M,N] = A[M,K] @ Bw[N,K]^T + bias  (optional relu)
#define LDS 20

__device__ __forceinline__ uint32_t f2tf(float x)
{
    uint32_t r;
    asm("cvt.rna.tf32.f32 %0, %1;" : "=r"(r) : "f"(x));
    return r;
}

__global__ void __launch_bounds__(256) gemm_tf32(
    const float* __restrict__ A, const float* __restrict__ Bw,
    const float* __restrict__ bias, float* __restrict__ C,
    int M, int N, int K, int relu)
{
    __shared__ float As[2][128 * LDS];
    __shared__ float Bs[2][128 * LDS];

    const int tid  = threadIdx.x;
    const int warp = tid >> 5, lane = tid & 31;
    const int wm = warp & 3, wn = warp >> 2;
    const int l4 = lane >> 2, lq = lane & 3;
    const int m0 = blockIdx.y * 128, n0 = blockIdx.x * 128;

    float acc[2][8][4];
    #pragma unroll
    for (int a = 0; a < 2; a++)
        #pragma unroll
        for (int b = 0; b < 8; b++)
            #pragma unroll
            for (int c = 0; c < 4; c++) acc[a][b][c] = 0.0f;

    #define STAGE(s, k0)                                                        \
    {                                                                           \
        _Pragma("unroll")                                                       \
        for (int u = 0; u < 2; u++) {                                           \
            int chunk = tid + u * 256;                                          \
            int row = chunk >> 2, c4 = chunk & 3;                               \
            const float* srcA = A + (size_t)(m0 + row) * K + (k0) + c4 * 4;     \
            uint32_t dstA = (uint32_t)__cvta_generic_to_shared(                 \
                                &As[s][row * LDS + c4 * 4]);                    \
            asm volatile("cp.async.cg.shared.global [%0], [%1], 16;"            \
                         :: "r"(dstA), "l"(srcA));                              \
            const float* srcB = Bw + (size_t)(n0 + row) * K + (k0) + c4 * 4;    \
            uint32_t dstB = (uint32_t)__cvta_generic_to_shared(                 \
                                &Bs[s][row * LDS + c4 * 4]);                    \
            asm volatile("cp.async.cg.shared.global [%0], [%1], 16;"            \
                         :: "r"(dstB), "l"(srcB));                              \
        }                                                                       \
        asm volatile("cp.async.commit_group;");                                 \
    }

    const int nk = K >> 4;
    STAGE(0, 0);
    for (int kt = 0; kt < nk; kt++) {
        if (kt + 1 < nk) {
            STAGE((kt + 1) & 1, (kt + 1) * 16);
            asm volatile("cp.async.wait_group 1;");
        } else {
            asm volatile("cp.async.wait_group 0;");
        }
        __syncthreads();
        const float* as = As[kt & 1];
        const float* bs = Bs[kt & 1];
        #pragma unroll
        for (int ks = 0; ks < 16; ks += 8) {
            uint32_t af[2][4], bf[8][2];
            #pragma unroll
            for (int mt = 0; mt < 2; mt++) {
                int rb = wm * 32 + mt * 16 + l4;
                af[mt][0] = f2tf(as[rb * LDS + ks + lq]);
                af[mt][1] = f2tf(as[(rb + 8) * LDS + ks + lq]);
                af[mt][2] = f2tf(as[rb * LDS + ks + lq + 4]);
                af[mt][3] = f2tf(as[(rb + 8) * LDS + ks + lq + 4]);
            }
            #pragma unroll
            for (int nt = 0; nt < 8; nt++) {
                int nb = wn * 64 + nt * 8 + l4;
                bf[nt][0] = f2tf(bs[nb * LDS + ks + lq]);
                bf[nt][1] = f2tf(bs[nb * LDS + ks + lq + 4]);
            }
            #pragma unroll
            for (int mt = 0; mt < 2; mt++)
                #pragma unroll
                for (int nt = 0; nt < 8; nt++) {
                    float* c = acc[mt][nt];
                    asm volatile(
                        "mma.sync.aligned.m16n8k8.row.col.f32.tf32.tf32.f32 "
                        "{%0,%1,%2,%3}, {%4,%5,%6,%7}, {%8,%9}, {%0,%1,%2,%3};"
                        : "+f"(c[0]), "+f"(c[1]), "+f"(c[2]), "+f"(c[3])
                        : "r"(af[mt][0]), "r"(af[mt][1]),
                          "r"(af[mt][2]), "r"(af[mt][3]),
                          "r"(bf[nt][0]), "r"(bf[nt][1]));
                }
        }
        __syncthreads();
    }

    #pragma unroll
    for (int mt = 0; mt < 2; mt++) {
        int row = m0 + wm * 32 + mt * 16 + l4;
        #pragma unroll
        for (int nt = 0; nt < 8; nt++) {
            int col = n0 + wn * 64 + nt * 8 + lq * 2;
            float b0 = bias[col], b1 = bias[col + 1];
            float v0 = acc[mt][nt][0] + b0, v1 = acc[mt][nt][1] + b1;
            float v2 = acc[mt][nt][2] + b0, v3 = acc[mt][nt][3] + b1;
            if (relu) {
                v0 = fmaxf(v0, 0.0f); v1 = fmaxf(v1, 0.0f);
                v2 = fmaxf(v2, 0.0f); v3 = fmaxf(v3, 0.0f);
            }
            *(float2*)&C[(size_t)row * N + col]       = make_float2(v0, v1);
            *(float2*)&C[(size_t)(row + 8) * N + col] = make_float2(v2, v3);
        }
    }
}

// ---------------- tiled sparse attention (flash-style, fp32) --------------
// One 256-thread block per (64-query tile, b, h). Keys for the tile live in
// [q0-WIN, q0+QT+WIN) -> <=5 aligned 64-chunks, plus one 8-wide "global
// columns" chunk (j%256==0) masked to exclude already-covered columns.
#define QT 64
#define CHK 64
#define SPAD 68
#define ATTN_SMEM (3 * QT * SPAD * 4)   // qs + kp(=ps) + vs

__global__ void __launch_bounds__(256) attn_tile_kernel()
{
    extern __shared__ float sm[];
    float* qs = sm;                  // [QT][SPAD]
    float* kp = sm + QT * SPAD;      // K chunk, reused as P
    float* vs = sm + 2 * QT * SPAD;  // V chunk

    const int q0  = blockIdx.x * QT;
    const int b   = blockIdx.y >> 3;
    const int h   = blockIdx.y & 7;
    const int tid = threadIdx.x;
    const int rt  = tid >> 4;        // 0..15: row group (4 rows)
    const int ct  = tid & 15;        // 0..15: col group (4 cols)

    // load + scale Q tile
    #pragma unroll
    for (int u = 0; u < 4; u++) {
        int idx = tid + u * 256;             // 1024 float4s
        int r = idx >> 4, c4 = idx & 15;
        float4 v = *(const float4*)&g_qkv[((size_t)(q0 + r) * BAT + b) * QKVE + h * HD + c4 * 4];
        v.x *= 0.125f; v.y *= 0.125f; v.z *= 0.125f; v.w *= 0.125f;
        *(float4*)&qs[r * SPAD + c4 * 4] = v;
    }

    float o[4][4];
    float m[4], l[4];
    #pragma unroll
    for (int rr = 0; rr < 4; rr++) {
        m[rr] = -1e30f; l[rr] = 0.0f;
        #pragma unroll
        for (int dd = 0; dd < 4; dd++) o[rr][dd] = 0.0f;
    }

    const int cov_lo = (q0 - WIN < 0) ? 0 : q0 - WIN;
    const int cov_hi = (q0 + QT + WIN > SEQ) ? SEQ : q0 + QT + WIN;
    const int nwchunk = (cov_hi - cov_lo) / CHK;       // 3..5

    for (int cix = 0; cix <= nwchunk; cix++) {
        const bool is_glob = (cix == nwchunk);
        const int j0 = cov_lo + cix * CHK;             // window chunk base
        __syncthreads();                               // prev PV done

        if (!is_glob) {
            #pragma unroll
            for (int u = 0; u < 4; u++) {
                int idx = tid + u * 256;
                int r = idx >> 4, c4 = idx & 15;
                size_t base = ((size_t)(j0 + r) * BAT + b) * QKVE + h * HD + c4 * 4;
                *(float4*)&kp[r * SPAD + c4 * 4] = *(const float4*)&g_qkv[base + EMB];
                *(float4*)&vs[r * SPAD + c4 * 4] = *(const float4*)&g_qkv[base + 2 * EMB];
            }
        } else if (tid < 128) {
            int r = tid >> 4, c4 = tid & 15;           // 8 global rows
            size_t base = ((size_t)(r * 256) * BAT + b) * QKVE + h * HD + c4 * 4;
            *(float4*)&kp[r * SPAD + c4 * 4] = *(const float4*)&g_qkv[base + EMB];
            *(float4*)&vs[r * SPAD + c4 * 4] = *(const float4*)&g_qkv[base + 2 * EMB];
        }
        __syncthreads();

        const int ncols = is_glob ? 8 : CHK;

        // --- scores: s[4][4] = Q(4 rows) . K(4 cols) ---
        float s[4][4];
        #pragma unroll
        for (int rr = 0; rr < 4; rr++)
            #pragma unroll
            for (int cc = 0; cc < 4; cc++) s[rr][cc] = 0.0f;
        #pragma unroll 4
        for (int k = 0; k < HD; k += 4) {
            float4 qv[4], kv[4];
            #pragma unroll
            for (int rr = 0; rr < 4; rr++)
                qv[rr] = *(const float4*)&qs[(rt * 4 + rr) * SPAD + k];
            #pragma unroll
            for (int cc = 0; cc < 4; cc++)
                kv[cc] = *(const float4*)&kp[(ct * 4 + cc) * SPAD + k];
            #pragma unroll
            for (int rr = 0; rr < 4; rr++)
                #pragma unroll
                for (int cc = 0; cc < 4; cc++)
                    s[rr][cc] += qv[rr].x * kv[cc].x + qv[rr].y * kv[cc].y
                               + qv[rr].z * kv[cc].z + qv[rr].w * kv[cc].w;
        }

        // --- mask + per-row chunk max ---
        float mc[4];
        #pragma unroll
        for (int rr = 0; rr < 4; rr++) {
            const int i = q0 + rt * 4 + rr;
            float mm = -1e30f;
            #pragma unroll
            for (int cc = 0; cc < 4; cc++) {
                const int c = ct * 4 + cc;
                bool ok;
                if (is_glob) {
                    const int j = c * 256;
                    ok = (c < 8) && (j < cov_lo || j >= cov_hi);
                } else {
                    const int j = j0 + c;
                    const int d = i - j;
                    ok = (d <= WIN && d >= -WIN) || ((j & 255) == 0);
                }
                if (!ok) s[rr][cc] = -1e30f;
                mm = fmaxf(mm, s[rr][cc]);
            }
            mc[rr] = mm;
        }
        #pragma unroll
        for (int off = 1; off < 16; off <<= 1)
            #pragma unroll
            for (int rr = 0; rr < 4; rr++)
                mc[rr] = fmaxf(mc[rr], __shfl_xor_sync(~0u, mc[rr], off));

        // --- flash update + p ---
        float psum[4];
        #pragma unroll
        for (int rr = 0; rr < 4; rr++) {
            float mn = fmaxf(m[rr], mc[rr]);
            float sc = __expf(m[rr] - mn);
            m[rr] = mn;
            l[rr] *= sc;
            #pragma unroll
            for (int dd = 0; dd < 4; dd++) o[rr][dd] *= sc;
            float ps = 0.0f;
            #pragma unroll
            for (int cc = 0; cc < 4; cc++) {
                float p = (s[rr][cc] > -1e29f) ? __expf(s[rr][cc] - mn) : 0.0f;
                s[rr][cc] = p;
                ps += p;
            }
            psum[rr] = ps;
        }
        #pragma unroll
        for (int off = 1; off < 16; off <<= 1)
            #pragma unroll
            for (int rr = 0; rr < 4; rr++)
                psum[rr] += __shfl_xor_sync(~0u, psum[rr], off);
        #pragma unroll
        for (int rr = 0; rr < 4; rr++) l[rr] += psum[rr];

        // --- stage P into kp (K no longer needed) ---
        __syncthreads();
        #pragma unroll
        for (int rr = 0; rr < 4; rr++)
            *(float4*)&kp[(rt * 4 + rr) * SPAD + ct * 4] =
                make_float4(s[rr][0], s[rr][1], s[rr][2], s[rr][3]);
        __syncthreads();

        // --- PV: o[4 rows][4 dims] += P . V  (thread dims = ct*4..) ---
        #pragma unroll 4
        for (int c = 0; c < ncols; c++) {
            float4 vv = *(const float4*)&vs[c * SPAD + ct * 4];
            #pragma unroll
            for (int rr = 0; rr < 4; rr++) {
                float pp = kp[(rt * 4 + rr) * SPAD + c];
                o[rr][0] += pp * vv.x; o[rr][1] += pp * vv.y;
                o[rr][2] += pp * vv.z; o[rr][3] += pp * vv.w;
            }
        }
    }

    // --- write out ---
    #pragma unroll
    for (int rr = 0; rr < 4; rr++) {
        const int row = q0 + rt * 4 + rr;
        const float inv = 1.0f / l[rr];
        *(float4*)&g_y[((size_t)row * BAT + b) * EMB + h * HD + ct * 4] =
            make_float4(o[rr][0] * inv, o[rr][1] * inv, o[rr][2] * inv, o[rr][3] * inv);
    }
}

// ---------------- fused residual add + layernorm --------------------------
__global__ void add_ln_kernel(const float* __restrict__ a,
                              const float* __restrict__ r,
                              const float* __restrict__ g,
                              const float* __restrict__ be,
                              float* __restrict__ out)
{
    const int row = blockIdx.x;
    const int tid = threadIdx.x;
    __shared__ float red[4];
    __shared__ float s_stat[2];

    float v[4];
    float s = 0.0f;
    #pragma unroll
    for (int u = 0; u < 4; u++) {
        int e = tid + u * 128;
        v[u] = a[(size_t)row * EMB + e] + r[(size_t)row * EMB + e];
        s += v[u];
    }
    #pragma unroll
    for (int o = 16; o; o >>= 1) s += __shfl_xor_sync(~0u, s, o);
    if ((tid & 31) == 0) red[tid >> 5] = s;
    __syncthreads();
    const float mean = (red[0] + red[1] + red[2] + red[3]) * (1.0f / EMB);
    __syncthreads();

    float s2 = 0.0f;
    #pragma unroll
    for (int u = 0; u < 4; u++) {
        float dl = v[u] - mean;
        s2 += dl * dl;
    }
    #pragma unroll
    for (int o = 16; o; o >>= 1) s2 += __shfl_xor_sync(~0u, s2, o);
    if ((tid & 31) == 0) red[tid >> 5] = s2;
    __syncthreads();
    if (tid == 0) s_stat[0] = (red[0] + red[1] + red[2] + red[3]) * (1.0f / EMB);
    __syncthreads();
    const float rstd = rsqrtf(s_stat[0] + 1e-5f);

    #pragma unroll
    for (int u = 0; u < 4; u++) {
        int e = tid + u * 128;
        out[(size_t)row * EMB + e] = (v[u] - mean) * rstd * g[e] + be[e];
    }
}

// ---------------- launch ---------------------------------------------------
extern "C" void kernel_launch(void* const* d_in, const int* in_sizes, int n_in,
                              void* d_out, int out_size)
{
    const float* x         = (const float*)d_in[0];
    const float* pos       = (const float*)d_in[1];
    const float* in_proj_w = (const float*)d_in[2];
    const float* in_proj_b = (const float*)d_in[3];
    const float* out_w     = (const float*)d_in[4];
    const float* out_b     = (const float*)d_in[5];
    const float* w1        = (const float*)d_in[6];
    const float* b1        = (const float*)d_in[7];
    const float* w2        = (const float*)d_in[8];
    const float* b2        = (const float*)d_in[9];
    const float* g1        = (const float*)d_in[10];
    const float* be1       = (const float*)d_in[11];
    const float* g2        = (const float*)d_in[12];
    const float* be2       = (const float*)d_in[13];
    float* out = (float*)d_out;

    float *xp, *qkv, *y, *tmp, *ln1, *ffh;
    cudaGetSymbolAddress((void**)&xp,  g_xp);
    cudaGetSymbolAddress((void**)&qkv, g_qkv);
    cudaGetSymbolAddress((void**)&y,   g_y);
    cudaGetSymbolAddress((void**)&tmp, g_tmp);
    cudaGetSymbolAddress((void**)&ln1, g_ln1);
    cudaGetSymbolAddress((void**)&ffh, g_ffh);

    cudaFuncSetAttribute(attn_tile_kernel,
                         cudaFuncAttributeMaxDynamicSharedMemorySize, ATTN_SMEM);

    // 1. x + pos
    add_pos_kernel<<<(TOK * EMB / 4) / 256, 256>>>(x, pos);

    // 2. QKV projection
    gemm_tf32<<<dim3(QKVE / 128, TOK / 128), 256>>>(xp, in_proj_w, in_proj_b, qkv,
                                                    TOK, QKVE, EMB, 0);

    // 3. tiled sparse attention
    attn_tile_kernel<<<dim3(SEQ / QT, BAT * NH), 256, ATTN_SMEM>>>();

    // 4. out projection
    gemm_tf32<<<dim3(EMB / 128, TOK / 128), 256>>>(y, out_w, out_b, tmp,
                                                   TOK, EMB, EMB, 0);

    // 5. residual + LN1
    add_ln_kernel<<<TOK, 128>>>(xp, tmp, g1, be1, ln1);

    // 6. FF1 + ReLU
    gemm_tf32<<<dim3(FFD / 128, TOK / 128), 256>>>(ln1, w1, b1, ffh,
                                                   TOK, FFD, EMB, 1);

    // 7. FF2
    gemm_tf32<<<dim3(EMB / 128, TOK / 128), 256>>>(ffh, w2, b2, tmp,
                                                   TOK, EMB, FFD, 0);

    // 8. residual + LN2 -> output
    add_ln_kernel<<<TOK, 128>>>(ln1, tmp, g2, be2, out);
}

// round 4
// speedup vs baseline: 4.7115x; 1.0702x over previous
#include <cuda_runtime.h>
#include <math.h>
#include <stdint.h>

#define SEQ 2048
#define BAT 4
#define EMB 512
#define NH  8
#define HD  64
#define FFD 2048
#define WIN 128
#define TOK (SEQ*BAT)            // 8192
#define QKVE (3*EMB)             // 1536

// ---------------- scratch (device globals; no allocation) ----------------
__device__ float g_xp [TOK*EMB];     // x + pos, full precision (residual 1)
__device__ float g_xpr[TOK*EMB];     // x + pos, tf32-rounded (QKV GEMM A)
__device__ float g_qkv[TOK*QKVE];    // qkv projection (fp32, attn input)
__device__ float g_y  [TOK*EMB];     // attention out, tf32-rounded (out-proj A)
__device__ float g_tmp[TOK*EMB];     // attn_out / ff_out (fp32, residual adds)
__device__ float g_ln1 [TOK*EMB];    // after LN1, full (residual 2)
__device__ float g_ln1r[TOK*EMB];    // after LN1, rounded (FF1 A)
__device__ float g_ffh[TOK*FFD];     // ff hidden, relu+rounded (FF2 A)
// rounded weights, packed: [in_proj_w | out_w | w1 | w2]
#define OFF_INPROJ 0
#define OFF_OUTW   (QKVE*EMB)                      // 786432
#define OFF_W1     (OFF_OUTW + EMB*EMB)            // 1048576
#define OFF_W2     (OFF_W1 + FFD*EMB)              // 2097152
__device__ float g_wr[OFF_W2 + EMB*FFD];

__device__ __forceinline__ uint32_t f2tf(float x)
{
    uint32_t r;
    asm("cvt.rna.tf32.f32 %0, %1;" : "=r"(r) : "f"(x));
    return r;
}
__device__ __forceinline__ float rnd_tf32(float x)
{
    return __uint_as_float(f2tf(x));
}

// ---------------- weight rounding (once per launch, cheap) ----------------
__global__ void round_copy(const float* __restrict__ src, float* __restrict__ dst)
{
    int idx = blockIdx.x * 256 + threadIdx.x;
    float4 v = ((const float4*)src)[idx];
    v.x = rnd_tf32(v.x); v.y = rnd_tf32(v.y);
    v.z = rnd_tf32(v.z); v.w = rnd_tf32(v.w);
    ((float4*)dst)[idx] = v;
}

// ---------------- x + pos (broadcast quirk: pos[0, b, :]) -----------------
__global__ void add_pos_kernel(const float* __restrict__ x,
                               const float* __restrict__ pos)
{
    int idx = blockIdx.x * 256 + threadIdx.x;      // over TOK*EMB/4 float4s
    int e4 = idx & (EMB / 4 - 1);
    int b  = (idx >> 7) & (BAT - 1);
    float4 xv = ((const float4*)x)[idx];
    float4 pv = ((const float4*)pos)[b * (EMB / 4) + e4];
    xv.x += pv.x; xv.y += pv.y; xv.z += pv.z; xv.w += pv.w;
    ((float4*)g_xp)[idx] = xv;
    float4 rv;
    rv.x = rnd_tf32(xv.x); rv.y = rnd_tf32(xv.y);
    rv.z = rnd_tf32(xv.z); rv.w = rnd_tf32(xv.w);
    ((float4*)g_xpr)[idx] = rv;
}

// ---------------- TF32 tensor-core GEMM (pre-rounded inputs) --------------
// C[M,N] = A[M,K] @ Bw[N,K]^T + bias.  mode: 0 = plain, 1 = relu+round.
// 128x128 tile, BK=16, 8 warps of 32x64, 3-stage cp.async ring.
#define LDS 20
#define NSTAGE 3
#define GEMM_SMEM (NSTAGE * 2 * 128 * LDS * 4)

__global__ void __launch_bounds__(256, 2) gemm_tf32(
    const float* __restrict__ A, const float* __restrict__ Bw,
    const float* __restrict__ bias, float* __restrict__ C,
    int M, int N, int K, int mode)
{
    extern __shared__ float gsm[];
    float* Asm = gsm;                       // [NSTAGE][128*LDS]
    float* Bsm = gsm + NSTAGE * 128 * LDS;

    const int tid  = threadIdx.x;
    const int warp = tid >> 5, lane = tid & 31;
    const int wm = warp & 3, wn = warp >> 2;
    const int l4 = lane >> 2, lq = lane & 3;
    const int m0 = blockIdx.y * 128, n0 = blockIdx.x * 128;

    float acc[2][8][4];
    #pragma unroll
    for (int a = 0; a < 2; a++)
        #pragma unroll
        for (int b = 0; b < 8; b++)
            #pragma unroll
            for (int c = 0; c < 4; c++) acc[a][b][c] = 0.0f;

    const int srow = tid >> 2, sc4 = (tid & 3) * 4;   // staging coords

    #define STAGE(s, k0)                                                        \
    {                                                                           \
        float* asb = Asm + (s) * 128 * LDS;                                     \
        float* bsb = Bsm + (s) * 128 * LDS;                                     \
        _Pragma("unroll")                                                       \
        for (int u = 0; u < 2; u++) {                                           \
            int row = srow + u * 64;                                            \
            const float* srcA = A + (size_t)(m0 + row) * K + (k0) + sc4;        \
            uint32_t dstA = (uint32_t)__cvta_generic_to_shared(                 \
                                &asb[row * LDS + sc4]);                         \
            asm volatile("cp.async.cg.shared.global [%0], [%1], 16;"            \
                         :: "r"(dstA), "l"(srcA));                              \
            const float* srcB = Bw + (size_t)(n0 + row) * K + (k0) + sc4;       \
            uint32_t dstB = (uint32_t)__cvta_generic_to_shared(                 \
                                &bsb[row * LDS + sc4]);                         \
            asm volatile("cp.async.cg.shared.global [%0], [%1], 16;"            \
                         :: "r"(dstB), "l"(srcB));                              \
        }                                                                       \
        asm volatile("cp.async.commit_group;");                                 \
    }

    const int nk = K >> 4;
    STAGE(0, 0);
    STAGE(1, 16);

    int buf = 0;
    for (int kt = 0; kt < nk; kt++) {
        if (kt + 1 < nk) asm volatile("cp.async.wait_group 1;");
        else             asm volatile("cp.async.wait_group 0;");
        __syncthreads();
        if (kt + 2 < nk) {
            int nb = buf + 2; if (nb >= NSTAGE) nb -= NSTAGE;
            STAGE(nb, (kt + 2) * 16);
        }
        const float* as = Asm + buf * 128 * LDS;
        const float* bs = Bsm + buf * 128 * LDS;
        #pragma unroll
        for (int ks = 0; ks < 16; ks += 8) {
            uint32_t af[2][4], bf[8][2];
            #pragma unroll
            for (int mt = 0; mt < 2; mt++) {
                int rb = wm * 32 + mt * 16 + l4;
                af[mt][0] = __float_as_uint(as[rb * LDS + ks + lq]);
                af[mt][1] = __float_as_uint(as[(rb + 8) * LDS + ks + lq]);
                af[mt][2] = __float_as_uint(as[rb * LDS + ks + lq + 4]);
                af[mt][3] = __float_as_uint(as[(rb + 8) * LDS + ks + lq + 4]);
            }
            #pragma unroll
            for (int nt = 0; nt < 8; nt++) {
                int nb = wn * 64 + nt * 8 + l4;
                bf[nt][0] = __float_as_uint(bs[nb * LDS + ks + lq]);
                bf[nt][1] = __float_as_uint(bs[nb * LDS + ks + lq + 4]);
            }
            #pragma unroll
            for (int mt = 0; mt < 2; mt++)
                #pragma unroll
                for (int nt = 0; nt < 8; nt++) {
                    float* c = acc[mt][nt];
                    asm volatile(
                        "mma.sync.aligned.m16n8k8.row.col.f32.tf32.tf32.f32 "
                        "{%0,%1,%2,%3}, {%4,%5,%6,%7}, {%8,%9}, {%0,%1,%2,%3};"
                        : "+f"(c[0]), "+f"(c[1]), "+f"(c[2]), "+f"(c[3])
                        : "r"(af[mt][0]), "r"(af[mt][1]),
                          "r"(af[mt][2]), "r"(af[mt][3]),
                          "r"(bf[nt][0]), "r"(bf[nt][1]));
                }
        }
        __syncthreads();
        buf++; if (buf >= NSTAGE) buf = 0;
    }

    #pragma unroll
    for (int mt = 0; mt < 2; mt++) {
        int row = m0 + wm * 32 + mt * 16 + l4;
        #pragma unroll
        for (int nt = 0; nt < 8; nt++) {
            int col = n0 + wn * 64 + nt * 8 + lq * 2;
            float b0 = bias[col], b1 = bias[col + 1];
            float v0 = acc[mt][nt][0] + b0, v1 = acc[mt][nt][1] + b1;
            float v2 = acc[mt][nt][2] + b0, v3 = acc[mt][nt][3] + b1;
            if (mode == 1) {
                v0 = rnd_tf32(fmaxf(v0, 0.0f)); v1 = rnd_tf32(fmaxf(v1, 0.0f));
                v2 = rnd_tf32(fmaxf(v2, 0.0f)); v3 = rnd_tf32(fmaxf(v3, 0.0f));
            }
            *(float2*)&C[(size_t)row * N + col]       = make_float2(v0, v1);
            *(float2*)&C[(size_t)(row + 8) * N + col] = make_float2(v2, v3);
        }
    }
}

// ---------------- tiled sparse attention (flash-style, fp32) --------------
#define QT 64
#define CHK 64
#define SPAD 68
#define ATTN_SMEM (3 * QT * SPAD * 4)

__global__ void __launch_bounds__(256) attn_tile_kernel()
{
    extern __shared__ float sm[];
    float* qs = sm;
    float* kp = sm + QT * SPAD;
    float* vs = sm + 2 * QT * SPAD;

    const int q0  = blockIdx.x * QT;
    const int b   = blockIdx.y >> 3;
    const int h   = blockIdx.y & 7;
    const int tid = threadIdx.x;
    const int rt  = tid >> 4;
    const int ct  = tid & 15;

    #pragma unroll
    for (int u = 0; u < 4; u++) {
        int idx = tid + u * 256;
        int r = idx >> 4, c4 = idx & 15;
        float4 v = *(const float4*)&g_qkv[((size_t)(q0 + r) * BAT + b) * QKVE + h * HD + c4 * 4];
        v.x *= 0.125f; v.y *= 0.125f; v.z *= 0.125f; v.w *= 0.125f;
        *(float4*)&qs[r * SPAD + c4 * 4] = v;
    }

    float o[4][4];
    float m[4], l[4];
    #pragma unroll
    for (int rr = 0; rr < 4; rr++) {
        m[rr] = -1e30f; l[rr] = 0.0f;
        #pragma unroll
        for (int dd = 0; dd < 4; dd++) o[rr][dd] = 0.0f;
    }

    const int cov_lo = (q0 - WIN < 0) ? 0 : q0 - WIN;
    const int cov_hi = (q0 + QT + WIN > SEQ) ? SEQ : q0 + QT + WIN;
    const int nwchunk = (cov_hi - cov_lo) / CHK;

    for (int cix = 0; cix <= nwchunk; cix++) {
        const bool is_glob = (cix == nwchunk);
        const int j0 = cov_lo + cix * CHK;
        __syncthreads();

        if (!is_glob) {
            #pragma unroll
            for (int u = 0; u < 4; u++) {
                int idx = tid + u * 256;
                int r = idx >> 4, c4 = idx & 15;
                size_t base = ((size_t)(j0 + r) * BAT + b) * QKVE + h * HD + c4 * 4;
                *(float4*)&kp[r * SPAD + c4 * 4] = *(const float4*)&g_qkv[base + EMB];
                *(float4*)&vs[r * SPAD + c4 * 4] = *(const float4*)&g_qkv[base + 2 * EMB];
            }
        } else if (tid < 128) {
            int r = tid >> 4, c4 = tid & 15;
            size_t base = ((size_t)(r * 256) * BAT + b) * QKVE + h * HD + c4 * 4;
            *(float4*)&kp[r * SPAD + c4 * 4] = *(const float4*)&g_qkv[base + EMB];
            *(float4*)&vs[r * SPAD + c4 * 4] = *(const float4*)&g_qkv[base + 2 * EMB];
        }
        __syncthreads();

        const int ncols = is_glob ? 8 : CHK;

        float s[4][4];
        #pragma unroll
        for (int rr = 0; rr < 4; rr++)
            #pragma unroll
            for (int cc = 0; cc < 4; cc++) s[rr][cc] = 0.0f;
        #pragma unroll 4
        for (int k = 0; k < HD; k += 4) {
            float4 qv[4], kv[4];
            #pragma unroll
            for (int rr = 0; rr < 4; rr++)
                qv[rr] = *(const float4*)&qs[(rt * 4 + rr) * SPAD + k];
            #pragma unroll
            for (int cc = 0; cc < 4; cc++)
                kv[cc] = *(const float4*)&kp[(ct * 4 + cc) * SPAD + k];
            #pragma unroll
            for (int rr = 0; rr < 4; rr++)
                #pragma unroll
                for (int cc = 0; cc < 4; cc++)
                    s[rr][cc] += qv[rr].x * kv[cc].x + qv[rr].y * kv[cc].y
                               + qv[rr].z * kv[cc].z + qv[rr].w * kv[cc].w;
        }

        float mc[4];
        #pragma unroll
        for (int rr = 0; rr < 4; rr++) {
            const int i = q0 + rt * 4 + rr;
            float mm = -1e30f;
            #pragma unroll
            for (int cc = 0; cc < 4; cc++) {
                const int c = ct * 4 + cc;
                bool ok;
                if (is_glob) {
                    const int j = c * 256;
                    ok = (c < 8) && (j < cov_lo || j >= cov_hi);
                } else {
                    const int j = j0 + c;
                    const int d = i - j;
                    ok = (d <= WIN && d >= -WIN) || ((j & 255) == 0);
                }
                if (!ok) s[rr][cc] = -1e30f;
                mm = fmaxf(mm, s[rr][cc]);
            }
            mc[rr] = mm;
        }
        #pragma unroll
        for (int off = 1; off < 16; off <<= 1)
            #pragma unroll
            for (int rr = 0; rr < 4; rr++)
                mc[rr] = fmaxf(mc[rr], __shfl_xor_sync(~0u, mc[rr], off));

        float psum[4];
        #pragma unroll
        for (int rr = 0; rr < 4; rr++) {
            float mn = fmaxf(m[rr], mc[rr]);
            float sc = __expf(m[rr] - mn);
            m[rr] = mn;
            l[rr] *= sc;
            #pragma unroll
            for (int dd = 0; dd < 4; dd++) o[rr][dd] *= sc;
            float ps = 0.0f;
            #pragma unroll
            for (int cc = 0; cc < 4; cc++) {
                float p = (s[rr][cc] > -1e29f) ? __expf(s[rr][cc] - mn) : 0.0f;
                s[rr][cc] = p;
                ps += p;
            }
            psum[rr] = ps;
        }
        #pragma unroll
        for (int off = 1; off < 16; off <<= 1)
            #pragma unroll
            for (int rr = 0; rr < 4; rr++)
                psum[rr] += __shfl_xor_sync(~0u, psum[rr], off);
        #pragma unroll
        for (int rr = 0; rr < 4; rr++) l[rr] += psum[rr];

        __syncthreads();
        #pragma unroll
        for (int rr = 0; rr < 4; rr++)
            *(float4*)&kp[(rt * 4 + rr) * SPAD + ct * 4] =
                make_float4(s[rr][0], s[rr][1], s[rr][2], s[rr][3]);
        __syncthreads();

        #pragma unroll 4
        for (int c = 0; c < ncols; c++) {
            float4 vv = *(const float4*)&vs[c * SPAD + ct * 4];
            #pragma unroll
            for (int rr = 0; rr < 4; rr++) {
                float pp = kp[(rt * 4 + rr) * SPAD + c];
                o[rr][0] += pp * vv.x; o[rr][1] += pp * vv.y;
                o[rr][2] += pp * vv.z; o[rr][3] += pp * vv.w;
            }
        }
    }

    #pragma unroll
    for (int rr = 0; rr < 4; rr++) {
        const int row = q0 + rt * 4 + rr;
        const float inv = 1.0f / l[rr];
        *(float4*)&g_y[((size_t)row * BAT + b) * EMB + h * HD + ct * 4] =
            make_float4(rnd_tf32(o[rr][0] * inv), rnd_tf32(o[rr][1] * inv),
                        rnd_tf32(o[rr][2] * inv), rnd_tf32(o[rr][3] * inv));
    }
}

// ---------------- fused residual add + layernorm --------------------------
// out = LN(a + r); out_r (optional) = tf32-rounded copy.
__global__ void add_ln_kernel(const float* __restrict__ a,
                              const float* __restrict__ r,
                              const float* __restrict__ g,
                              const float* __restrict__ be,
                              float* __restrict__ out,
                              float* __restrict__ out_r)
{
    const int row = blockIdx.x;
    const int tid = threadIdx.x;
    __shared__ float red[4];
    __shared__ float s_stat[2];

    float v[4];
    float s = 0.0f;
    #pragma unroll
    for (int u = 0; u < 4; u++) {
        int e = tid + u * 128;
        v[u] = a[(size_t)row * EMB + e] + r[(size_t)row * EMB + e];
        s += v[u];
    }
    #pragma unroll
    for (int o = 16; o; o >>= 1) s += __shfl_xor_sync(~0u, s, o);
    if ((tid & 31) == 0) red[tid >> 5] = s;
    __syncthreads();
    const float mean = (red[0] + red[1] + red[2] + red[3]) * (1.0f / EMB);
    __syncthreads();

    float s2 = 0.0f;
    #pragma unroll
    for (int u = 0; u < 4; u++) {
        float dl = v[u] - mean;
        s2 += dl * dl;
    }
    #pragma unroll
    for (int o = 16; o; o >>= 1) s2 += __shfl_xor_sync(~0u, s2, o);
    if ((tid & 31) == 0) red[tid >> 5] = s2;
    __syncthreads();
    if (tid == 0) s_stat[0] = (red[0] + red[1] + red[2] + red[3]) * (1.0f / EMB);
    __syncthreads();
    const float rstd = rsqrtf(s_stat[0] + 1e-5f);

    #pragma unroll
    for (int u = 0; u < 4; u++) {
        int e = tid + u * 128;
        float ov = (v[u] - mean) * rstd * g[e] + be[e];
        out[(size_t)row * EMB + e] = ov;
        if (out_r) out_r[(size_t)row * EMB + e] = rnd_tf32(ov);
    }
}

// ---------------- launch ---------------------------------------------------
extern "C" void kernel_launch(void* const* d_in, const int* in_sizes, int n_in,
                              void* d_out, int out_size)
{
    const float* x         = (const float*)d_in[0];
    const float* pos       = (const float*)d_in[1];
    const float* in_proj_w = (const float*)d_in[2];
    const float* in_proj_b = (const float*)d_in[3];
    const float* out_w     = (const float*)d_in[4];
    const float* out_b     = (const float*)d_in[5];
    const float* w1        = (const float*)d_in[6];
    const float* b1        = (const float*)d_in[7];
    const float* w2        = (const float*)d_in[8];
    const float* b2        = (const float*)d_in[9];
    const float* g1        = (const float*)d_in[10];
    const float* be1       = (const float*)d_in[11];
    const float* g2        = (const float*)d_in[12];
    const float* be2       = (const float*)d_in[13];
    float* out = (float*)d_out;

    float *xpr, *qkv, *y, *tmp, *ln1, *ln1r, *ffh, *wr, *xp;
    cudaGetSymbolAddress((void**)&xp,   g_xp);
    cudaGetSymbolAddress((void**)&xpr,  g_xpr);
    cudaGetSymbolAddress((void**)&qkv,  g_qkv);
    cudaGetSymbolAddress((void**)&y,    g_y);
    cudaGetSymbolAddress((void**)&tmp,  g_tmp);
    cudaGetSymbolAddress((void**)&ln1,  g_ln1);
    cudaGetSymbolAddress((void**)&ln1r, g_ln1r);
    cudaGetSymbolAddress((void**)&ffh,  g_ffh);
    cudaGetSymbolAddress((void**)&wr,   g_wr);

    cudaFuncSetAttribute(attn_tile_kernel,
                         cudaFuncAttributeMaxDynamicSharedMemorySize, ATTN_SMEM);
    cudaFuncSetAttribute(gemm_tf32,
                         cudaFuncAttributeMaxDynamicSharedMemorySize, GEMM_SMEM);

    // 0. round weights to tf32 (once per launch)
    round_copy<<<(QKVE * EMB / 4) / 256, 256>>>(in_proj_w, wr + OFF_INPROJ);
    round_copy<<<(EMB * EMB / 4) / 256, 256>>>(out_w, wr + OFF_OUTW);
    round_copy<<<(FFD * EMB / 4) / 256, 256>>>(w1, wr + OFF_W1);
    round_copy<<<(EMB * FFD / 4) / 256, 256>>>(w2, wr + OFF_W2);

    // 1. x + pos (full + rounded)
    add_pos_kernel<<<(TOK * EMB / 4) / 256, 256>>>(x, pos);

    // 2. QKV projection
    gemm_tf32<<<dim3(QKVE / 128, TOK / 128), 256, GEMM_SMEM>>>(
        xpr, wr + OFF_INPROJ, in_proj_b, qkv, TOK, QKVE, EMB, 0);

    // 3. tiled sparse attention (writes rounded g_y)
    attn_tile_kernel<<<dim3(SEQ / QT, BAT * NH), 256, ATTN_SMEM>>>();

    // 4. out projection
    gemm_tf32<<<dim3(EMB / 128, TOK / 128), 256, GEMM_SMEM>>>(
        y, wr + OFF_OUTW, out_b, tmp, TOK, EMB, EMB, 0);

    // 5. residual + LN1 (full + rounded)
    add_ln_kernel<<<TOK, 128>>>(xp, tmp, g1, be1, ln1, ln1r);

    // 6. FF1 + ReLU (epilogue rounds)
    gemm_tf32<<<dim3(FFD / 128, TOK / 128), 256, GEMM_SMEM>>>(
        ln1r, wr + OFF_W1, b1, ffh, TOK, FFD, EMB, 1);

    // 7. FF2
    gemm_tf32<<<dim3(EMB / 128, TOK / 128), 256, GEMM_SMEM>>>(
        ffh, wr + OFF_W2, b2, tmp, TOK, EMB, FFD, 0);

    // 8. residual + LN2 -> output
    add_ln_kernel<<<TOK, 128>>>(ln1, tmp, g2, be2, out, nullptr);
}

// round 5
// speedup vs baseline: 5.1540x; 1.0939x over previous
#include <cuda_runtime.h>
#include <math.h>
#include <stdint.h>

#define SEQ 2048
#define BAT 4
#define EMB 512
#define NH  8
#define HD  64
#define FFD 2048
#define WIN 128
#define TOK (SEQ*BAT)            // 8192
#define QKVE (3*EMB)             // 1536

// ---------------- scratch (device globals; no allocation) ----------------
__device__ float g_xp [TOK*EMB];     // x + pos, full precision (residual 1)
__device__ float g_xpr[TOK*EMB];     // x + pos, tf32-rounded (QKV GEMM A)
__device__ float g_qkv[TOK*QKVE];    // qkv projection (fp32, attn input)
__device__ float g_y  [TOK*EMB];     // attention out, tf32-rounded (out-proj A)
__device__ float g_tmp[TOK*EMB];     // attn_out / ff_out (fp32, residual adds)
__device__ float g_ln1 [TOK*EMB];    // after LN1, full (residual 2)
__device__ float g_ln1r[TOK*EMB];    // after LN1, rounded (FF1 A)
__device__ float g_ffh[TOK*FFD];     // ff hidden, relu+rounded (FF2 A)
// rounded weights, packed: [in_proj_w | out_w | w1 | w2]
#define OFF_INPROJ 0
#define OFF_OUTW   (QKVE*EMB)
#define OFF_W1     (OFF_OUTW + EMB*EMB)
#define OFF_W2     (OFF_W1 + FFD*EMB)
__device__ float g_wr[OFF_W2 + EMB*FFD];

__device__ __forceinline__ uint32_t f2tf(float x)
{
    uint32_t r;
    asm("cvt.rna.tf32.f32 %0, %1;" : "=r"(r) : "f"(x));
    return r;
}
__device__ __forceinline__ float rnd_tf32(float x)
{
    return __uint_as_float(f2tf(x));
}

// ---------------- weight rounding (once per launch, cheap) ----------------
__global__ void round_copy(const float* __restrict__ src, float* __restrict__ dst)
{
    int idx = blockIdx.x * 256 + threadIdx.x;
    float4 v = ((const float4*)src)[idx];
    v.x = rnd_tf32(v.x); v.y = rnd_tf32(v.y);
    v.z = rnd_tf32(v.z); v.w = rnd_tf32(v.w);
    ((float4*)dst)[idx] = v;
}

// ---------------- x + pos (broadcast quirk: pos[0, b, :]) -----------------
__global__ void add_pos_kernel(const float* __restrict__ x,
                               const float* __restrict__ pos)
{
    int idx = blockIdx.x * 256 + threadIdx.x;
    int e4 = idx & (EMB / 4 - 1);
    int b  = (idx >> 7) & (BAT - 1);
    float4 xv = ((const float4*)x)[idx];
    float4 pv = ((const float4*)pos)[b * (EMB / 4) + e4];
    xv.x += pv.x; xv.y += pv.y; xv.z += pv.z; xv.w += pv.w;
    ((float4*)g_xp)[idx] = xv;
    float4 rv;
    rv.x = rnd_tf32(xv.x); rv.y = rnd_tf32(xv.y);
    rv.z = rnd_tf32(xv.z); rv.w = rnd_tf32(xv.w);
    ((float4*)g_xpr)[idx] = rv;
}

// ---------------- TF32 tensor-core GEMM (ldmatrix fragments) --------------
// C[M,N] = A[M,K] @ Bw[N,K]^T + bias.  mode: 0 = plain, 1 = relu+round.
// 128x128 tile, BK=16, 8 warps of 32x64, 4-stage cp.async ring, 1 barrier/tile.
#define LDS 20
#define NSTAGE 4
#define STG_SZ (128 * LDS)
#define GEMM_SMEM (NSTAGE * 2 * STG_SZ * 4)

#define LDSM4(d, addr)                                                          \
    asm volatile("ldmatrix.sync.aligned.m8n8.x4.shared.b16 {%0,%1,%2,%3}, [%4];"\
                 : "=r"((d)[0]), "=r"((d)[1]), "=r"((d)[2]), "=r"((d)[3])       \
                 : "r"(addr))

__global__ void __launch_bounds__(256, 2) gemm_tf32(
    const float* __restrict__ A, const float* __restrict__ Bw,
    const float* __restrict__ bias, float* __restrict__ C,
    int M, int N, int K, int mode)
{
    extern __shared__ float gsm[];
    float* Asm = gsm;                       // [NSTAGE][STG_SZ]
    float* Bsm = gsm + NSTAGE * STG_SZ;

    const int tid  = threadIdx.x;
    const int warp = tid >> 5, lane = tid & 31;
    const int wm = warp & 3, wn = warp >> 2;
    const int l4 = lane >> 2, lq = lane & 3;
    const int m0 = blockIdx.y * 128, n0 = blockIdx.x * 128;

    float acc[2][8][4];
    #pragma unroll
    for (int a = 0; a < 2; a++)
        #pragma unroll
        for (int b = 0; b < 8; b++)
            #pragma unroll
            for (int c = 0; c < 4; c++) acc[a][b][c] = 0.0f;

    // ldmatrix per-thread row addresses (byte offsets within one stage)
    const int g8 = lane >> 3, r8 = lane & 7;
    uint32_t a_off[2], b_off[4];
    #pragma unroll
    for (int mt = 0; mt < 2; mt++)
        a_off[mt] = ((wm * 32 + mt * 16 + (g8 & 1) * 8 + r8) * LDS
                     + (g8 >> 1) * 4) * 4;
    #pragma unroll
    for (int nt2 = 0; nt2 < 4; nt2++)
        b_off[nt2] = ((wn * 64 + nt2 * 16 + (g8 >> 1) * 8 + r8) * LDS
                      + (g8 & 1) * 4) * 4;
    const uint32_t smA = (uint32_t)__cvta_generic_to_shared(Asm);
    const uint32_t smB = (uint32_t)__cvta_generic_to_shared(Bsm);

    const int srow = tid >> 2, sc4 = (tid & 3) * 4;   // staging coords

    #define STAGE(s, k0)                                                        \
    {                                                                           \
        float* asb = Asm + (s) * STG_SZ;                                        \
        float* bsb = Bsm + (s) * STG_SZ;                                        \
        _Pragma("unroll")                                                       \
        for (int u = 0; u < 2; u++) {                                           \
            int row = srow + u * 64;                                            \
            const float* srcA = A + (size_t)(m0 + row) * K + (k0) + sc4;        \
            uint32_t dstA = (uint32_t)__cvta_generic_to_shared(                 \
                                &asb[row * LDS + sc4]);                         \
            asm volatile("cp.async.cg.shared.global [%0], [%1], 16;"            \
                         :: "r"(dstA), "l"(srcA));                              \
            const float* srcB = Bw + (size_t)(n0 + row) * K + (k0) + sc4;       \
            uint32_t dstB = (uint32_t)__cvta_generic_to_shared(                 \
                                &bsb[row * LDS + sc4]);                         \
            asm volatile("cp.async.cg.shared.global [%0], [%1], 16;"            \
                         :: "r"(dstB), "l"(srcB));                              \
        }                                                                       \
        asm volatile("cp.async.commit_group;");                                 \
    }

    const int nk = K >> 4;
    STAGE(0, 0);
    STAGE(1, 16);

    int buf = 0;
    for (int kt = 0; kt < nk; kt++) {
        if (kt + 1 < nk) asm volatile("cp.async.wait_group 1;");
        else             asm volatile("cp.async.wait_group 0;");
        __syncthreads();
        if (kt + 2 < nk) {
            int nb = buf + 2; if (nb >= NSTAGE) nb -= NSTAGE;
            STAGE(nb, (kt + 2) * 16);
        }
        const uint32_t baseA = smA + buf * (STG_SZ * 4);
        const uint32_t baseB = smB + buf * (STG_SZ * 4);
        #pragma unroll
        for (int ks = 0; ks < 16; ks += 8) {
            uint32_t af[2][4], bf4[4][4];
            #pragma unroll
            for (int mt = 0; mt < 2; mt++)
                LDSM4(af[mt], baseA + a_off[mt] + ks * 4);
            #pragma unroll
            for (int nt2 = 0; nt2 < 4; nt2++)
                LDSM4(bf4[nt2], baseB + b_off[nt2] + ks * 4);
            #pragma unroll
            for (int mt = 0; mt < 2; mt++)
                #pragma unroll
                for (int nt = 0; nt < 8; nt++) {
                    float* c = acc[mt][nt];
                    const uint32_t b0 = bf4[nt >> 1][(nt & 1) * 2];
                    const uint32_t b1 = bf4[nt >> 1][(nt & 1) * 2 + 1];
                    asm volatile(
                        "mma.sync.aligned.m16n8k8.row.col.f32.tf32.tf32.f32 "
                        "{%0,%1,%2,%3}, {%4,%5,%6,%7}, {%8,%9}, {%0,%1,%2,%3};"
                        : "+f"(c[0]), "+f"(c[1]), "+f"(c[2]), "+f"(c[3])
                        : "r"(af[mt][0]), "r"(af[mt][1]),
                          "r"(af[mt][2]), "r"(af[mt][3]),
                          "r"(b0), "r"(b1));
                }
        }
        buf++; if (buf >= NSTAGE) buf = 0;
    }
    __syncthreads();

    #pragma unroll
    for (int mt = 0; mt < 2; mt++) {
        int row = m0 + wm * 32 + mt * 16 + l4;
        #pragma unroll
        for (int nt = 0; nt < 8; nt++) {
            int col = n0 + wn * 64 + nt * 8 + lq * 2;
            float b0 = bias[col], b1 = bias[col + 1];
            float v0 = acc[mt][nt][0] + b0, v1 = acc[mt][nt][1] + b1;
            float v2 = acc[mt][nt][2] + b0, v3 = acc[mt][nt][3] + b1;
            if (mode == 1) {
                v0 = rnd_tf32(fmaxf(v0, 0.0f)); v1 = rnd_tf32(fmaxf(v1, 0.0f));
                v2 = rnd_tf32(fmaxf(v2, 0.0f)); v3 = rnd_tf32(fmaxf(v3, 0.0f));
            }
            *(float2*)&C[(size_t)row * N + col]       = make_float2(v0, v1);
            *(float2*)&C[(size_t)(row + 8) * N + col] = make_float2(v2, v3);
        }
    }
}

// ---------------- tiled sparse attention (flash-style, fp32) --------------
#define QT 64
#define CHK 64
#define SPAD 68
#define ATTN_SMEM (3 * QT * SPAD * 4)

__global__ void __launch_bounds__(256) attn_tile_kernel()
{
    extern __shared__ float sm[];
    float* qs = sm;
    float* kp = sm + QT * SPAD;
    float* vs = sm + 2 * QT * SPAD;

    const int q0  = blockIdx.x * QT;
    const int b   = blockIdx.y >> 3;
    const int h   = blockIdx.y & 7;
    const int tid = threadIdx.x;
    const int rt  = tid >> 4;
    const int ct  = tid & 15;

    #pragma unroll
    for (int u = 0; u < 4; u++) {
        int idx = tid + u * 256;
        int r = idx >> 4, c4 = idx & 15;
        float4 v = *(const float4*)&g_qkv[((size_t)(q0 + r) * BAT + b) * QKVE + h * HD + c4 * 4];
        v.x *= 0.125f; v.y *= 0.125f; v.z *= 0.125f; v.w *= 0.125f;
        *(float4*)&qs[r * SPAD + c4 * 4] = v;
    }

    float o[4][4];
    float m[4], l[4];
    #pragma unroll
    for (int rr = 0; rr < 4; rr++) {
        m[rr] = -1e30f; l[rr] = 0.0f;
        #pragma unroll
        for (int dd = 0; dd < 4; dd++) o[rr][dd] = 0.0f;
    }

    const int cov_lo = (q0 - WIN < 0) ? 0 : q0 - WIN;
    const int cov_hi = (q0 + QT + WIN > SEQ) ? SEQ : q0 + QT + WIN;
    const int nwchunk = (cov_hi - cov_lo) / CHK;

    for (int cix = 0; cix <= nwchunk; cix++) {
        const bool is_glob = (cix == nwchunk);
        const int j0 = cov_lo + cix * CHK;
        __syncthreads();

        if (!is_glob) {
            #pragma unroll
            for (int u = 0; u < 4; u++) {
                int idx = tid + u * 256;
                int r = idx >> 4, c4 = idx & 15;
                size_t base = ((size_t)(j0 + r) * BAT + b) * QKVE + h * HD + c4 * 4;
                *(float4*)&kp[r * SPAD + c4 * 4] = *(const float4*)&g_qkv[base + EMB];
                *(float4*)&vs[r * SPAD + c4 * 4] = *(const float4*)&g_qkv[base + 2 * EMB];
            }
        } else if (tid < 128) {
            int r = tid >> 4, c4 = tid & 15;
            size_t base = ((size_t)(r * 256) * BAT + b) * QKVE + h * HD + c4 * 4;
            *(float4*)&kp[r * SPAD + c4 * 4] = *(const float4*)&g_qkv[base + EMB];
            *(float4*)&vs[r * SPAD + c4 * 4] = *(const float4*)&g_qkv[base + 2 * EMB];
        }
        __syncthreads();

        const int ncols = is_glob ? 8 : CHK;

        float s[4][4];
        #pragma unroll
        for (int rr = 0; rr < 4; rr++)
            #pragma unroll
            for (int cc = 0; cc < 4; cc++) s[rr][cc] = 0.0f;
        #pragma unroll 4
        for (int k = 0; k < HD; k += 4) {
            float4 qv[4], kv[4];
            #pragma unroll
            for (int rr = 0; rr < 4; rr++)
                qv[rr] = *(const float4*)&qs[(rt * 4 + rr) * SPAD + k];
            #pragma unroll
            for (int cc = 0; cc < 4; cc++)
                kv[cc] = *(const float4*)&kp[(ct * 4 + cc) * SPAD + k];
            #pragma unroll
            for (int rr = 0; rr < 4; rr++)
                #pragma unroll
                for (int cc = 0; cc < 4; cc++)
                    s[rr][cc] += qv[rr].x * kv[cc].x + qv[rr].y * kv[cc].y
                               + qv[rr].z * kv[cc].z + qv[rr].w * kv[cc].w;
        }

        float mc[4];
        #pragma unroll
        for (int rr = 0; rr < 4; rr++) {
            const int i = q0 + rt * 4 + rr;
            float mm = -1e30f;
            #pragma unroll
            for (int cc = 0; cc < 4; cc++) {
                const int c = ct * 4 + cc;
                bool ok;
                if (is_glob) {
                    const int j = c * 256;
                    ok = (c < 8) && (j < cov_lo || j >= cov_hi);
                } else {
                    const int j = j0 + c;
                    const int d = i - j;
                    ok = (d <= WIN && d >= -WIN) || ((j & 255) == 0);
                }
                if (!ok) s[rr][cc] = -1e30f;
                mm = fmaxf(mm, s[rr][cc]);
            }
            mc[rr] = mm;
        }
        #pragma unroll
        for (int off = 1; off < 16; off <<= 1)
            #pragma unroll
            for (int rr = 0; rr < 4; rr++)
                mc[rr] = fmaxf(mc[rr], __shfl_xor_sync(~0u, mc[rr], off));

        float psum[4];
        #pragma unroll
        for (int rr = 0; rr < 4; rr++) {
            float mn = fmaxf(m[rr], mc[rr]);
            float sc = __expf(m[rr] - mn);
            m[rr] = mn;
            l[rr] *= sc;
            #pragma unroll
            for (int dd = 0; dd < 4; dd++) o[rr][dd] *= sc;
            float ps = 0.0f;
            #pragma unroll
            for (int cc = 0; cc < 4; cc++) {
                float p = (s[rr][cc] > -1e29f) ? __expf(s[rr][cc] - mn) : 0.0f;
                s[rr][cc] = p;
                ps += p;
            }
            psum[rr] = ps;
        }
        #pragma unroll
        for (int off = 1; off < 16; off <<= 1)
            #pragma unroll
            for (int rr = 0; rr < 4; rr++)
                psum[rr] += __shfl_xor_sync(~0u, psum[rr], off);
        #pragma unroll
        for (int rr = 0; rr < 4; rr++) l[rr] += psum[rr];

        __syncthreads();
        #pragma unroll
        for (int rr = 0; rr < 4; rr++)
            *(float4*)&kp[(rt * 4 + rr) * SPAD + ct * 4] =
                make_float4(s[rr][0], s[rr][1], s[rr][2], s[rr][3]);
        __syncthreads();

        #pragma unroll 4
        for (int c = 0; c < ncols; c++) {
            float4 vv = *(const float4*)&vs[c * SPAD + ct * 4];
            #pragma unroll
            for (int rr = 0; rr < 4; rr++) {
                float pp = kp[(rt * 4 + rr) * SPAD + c];
                o[rr][0] += pp * vv.x; o[rr][1] += pp * vv.y;
                o[rr][2] += pp * vv.z; o[rr][3] += pp * vv.w;
            }
        }
    }

    #pragma unroll
    for (int rr = 0; rr < 4; rr++) {
        const int row = q0 + rt * 4 + rr;
        const float inv = 1.0f / l[rr];
        *(float4*)&g_y[((size_t)row * BAT + b) * EMB + h * HD + ct * 4] =
            make_float4(rnd_tf32(o[rr][0] * inv), rnd_tf32(o[rr][1] * inv),
                        rnd_tf32(o[rr][2] * inv), rnd_tf32(o[rr][3] * inv));
    }
}

// ---------------- fused residual add + layernorm --------------------------
__global__ void add_ln_kernel(const float* __restrict__ a,
                              const float* __restrict__ r,
                              const float* __restrict__ g,
                              const float* __restrict__ be,
                              float* __restrict__ out,
                              float* __restrict__ out_r)
{
    const int row = blockIdx.x;
    const int tid = threadIdx.x;
    __shared__ float red[4];
    __shared__ float s_stat[2];

    float v[4];
    float s = 0.0f;
    #pragma unroll
    for (int u = 0; u < 4; u++) {
        int e = tid + u * 128;
        v[u] = a[(size_t)row * EMB + e] + r[(size_t)row * EMB + e];
        s += v[u];
    }
    #pragma unroll
    for (int o = 16; o; o >>= 1) s += __shfl_xor_sync(~0u, s, o);
    if ((tid & 31) == 0) red[tid >> 5] = s;
    __syncthreads();
    const float mean = (red[0] + red[1] + red[2] + red[3]) * (1.0f / EMB);
    __syncthreads();

    float s2 = 0.0f;
    #pragma unroll
    for (int u = 0; u < 4; u++) {
        float dl = v[u] - mean;
        s2 += dl * dl;
    }
    #pragma unroll
    for (int o = 16; o; o >>= 1) s2 += __shfl_xor_sync(~0u, s2, o);
    if ((tid & 31) == 0) red[tid >> 5] = s2;
    __syncthreads();
    if (tid == 0) s_stat[0] = (red[0] + red[1] + red[2] + red[3]) * (1.0f / EMB);
    __syncthreads();
    const float rstd = rsqrtf(s_stat[0] + 1e-5f);

    #pragma unroll
    for (int u = 0; u < 4; u++) {
        int e = tid + u * 128;
        float ov = (v[u] - mean) * rstd * g[e] + be[e];
        out[(size_t)row * EMB + e] = ov;
        if (out_r) out_r[(size_t)row * EMB + e] = rnd_tf32(ov);
    }
}

// ---------------- launch ---------------------------------------------------
extern "C" void kernel_launch(void* const* d_in, const int* in_sizes, int n_in,
                              void* d_out, int out_size)
{
    const float* x         = (const float*)d_in[0];
    const float* pos       = (const float*)d_in[1];
    const float* in_proj_w = (const float*)d_in[2];
    const float* in_proj_b = (const float*)d_in[3];
    const float* out_w     = (const float*)d_in[4];
    const float* out_b     = (const float*)d_in[5];
    const float* w1        = (const float*)d_in[6];
    const float* b1        = (const float*)d_in[7];
    const float* w2        = (const float*)d_in[8];
    const float* b2        = (const float*)d_in[9];
    const float* g1        = (const float*)d_in[10];
    const float* be1       = (const float*)d_in[11];
    const float* g2        = (const float*)d_in[12];
    const float* be2       = (const float*)d_in[13];
    float* out = (float*)d_out;

    float *xpr, *qkv, *y, *tmp, *ln1, *ln1r, *ffh, *wr, *xp;
    cudaGetSymbolAddress((void**)&xp,   g_xp);
    cudaGetSymbolAddress((void**)&xpr,  g_xpr);
    cudaGetSymbolAddress((void**)&qkv,  g_qkv);
    cudaGetSymbolAddress((void**)&y,    g_y);
    cudaGetSymbolAddress((void**)&tmp,  g_tmp);
    cudaGetSymbolAddress((void**)&ln1,  g_ln1);
    cudaGetSymbolAddress((void**)&ln1r, g_ln1r);
    cudaGetSymbolAddress((void**)&ffh,  g_ffh);
    cudaGetSymbolAddress((void**)&wr,   g_wr);

    cudaFuncSetAttribute(attn_tile_kernel,
                         cudaFuncAttributeMaxDynamicSharedMemorySize, ATTN_SMEM);
    cudaFuncSetAttribute(gemm_tf32,
                         cudaFuncAttributeMaxDynamicSharedMemorySize, GEMM_SMEM);

    // 0. round weights to tf32 (once per launch)
    round_copy<<<(QKVE * EMB / 4) / 256, 256>>>(in_proj_w, wr + OFF_INPROJ);
    round_copy<<<(EMB * EMB / 4) / 256, 256>>>(out_w, wr + OFF_OUTW);
    round_copy<<<(FFD * EMB / 4) / 256, 256>>>(w1, wr + OFF_W1);
    round_copy<<<(EMB * FFD / 4) / 256, 256>>>(w2, wr + OFF_W2);

    // 1. x + pos (full + rounded)
    add_pos_kernel<<<(TOK * EMB / 4) / 256, 256>>>(x, pos);

    // 2. QKV projection
    gemm_tf32<<<dim3(QKVE / 128, TOK / 128), 256, GEMM_SMEM>>>(
        xpr, wr + OFF_INPROJ, in_proj_b, qkv, TOK, QKVE, EMB, 0);

    // 3. tiled sparse attention (writes rounded g_y)
    attn_tile_kernel<<<dim3(SEQ / QT, BAT * NH), 256, ATTN_SMEM>>>();

    // 4. out projection
    gemm_tf32<<<dim3(EMB / 128, TOK / 128), 256, GEMM_SMEM>>>(
        y, wr + OFF_OUTW, out_b, tmp, TOK, EMB, EMB, 0);

    // 5. residual + LN1 (full + rounded)
    add_ln_kernel<<<TOK, 128>>>(xp, tmp, g1, be1, ln1, ln1r);

    // 6. FF1 + ReLU (epilogue rounds)
    gemm_tf32<<<dim3(FFD / 128, TOK / 128), 256, GEMM_SMEM>>>(
        ln1r, wr + OFF_W1, b1, ffh, TOK, FFD, EMB, 1);

    // 7. FF2
    gemm_tf32<<<dim3(EMB / 128, TOK / 128), 256, GEMM_SMEM>>>(
        ffh, wr + OFF_W2, b2, tmp, TOK, EMB, FFD, 0);

    // 8. residual + LN2 -> output
    add_ln_kernel<<<TOK, 128>>>(ln1, tmp, g2, be2, out, nullptr);
}

// round 6
// speedup vs baseline: 7.3692x; 1.4298x over previous
#include <cuda_runtime.h>
#include <math.h>
#include <stdint.h>

#define SEQ 2048
#define BAT 4
#define EMB 512
#define NH  8
#define HD  64
#define FFD 2048
#define WIN 128
#define TOK (SEQ*BAT)            // 8192
#define QKVE (3*EMB)             // 1536

// ---------------- scratch (device globals; no allocation) ----------------
__device__ float g_xp [TOK*EMB];     // x + pos, full precision (residual 1)
__device__ float g_xpr[TOK*EMB];     // x + pos, tf32-rounded (QKV GEMM A)
__device__ float g_qkv[TOK*QKVE];    // qkv projection (fp32, attn input)
__device__ float g_y  [TOK*EMB];     // attention out, tf32-rounded (out-proj A)
__device__ float g_tmp[TOK*EMB];     // attn_out / ff_out (fp32, residual adds)
__device__ float g_ln1 [TOK*EMB];    // after LN1, full (residual 2)
__device__ float g_ln1r[TOK*EMB];    // after LN1, rounded (FF1 A)
__device__ float g_ffh[TOK*FFD];     // ff hidden, relu+rounded (FF2 A)
// rounded weights, packed: [in_proj_w | out_w | w1 | w2]
#define OFF_INPROJ 0
#define OFF_OUTW   (QKVE*EMB)
#define OFF_W1     (OFF_OUTW + EMB*EMB)
#define OFF_W2     (OFF_W1 + FFD*EMB)
#define W_TOTAL    (OFF_W2 + EMB*FFD)
__device__ float g_wr[W_TOTAL];

__device__ __forceinline__ uint32_t f2tf(float x)
{
    uint32_t r;
    asm("cvt.rna.tf32.f32 %0, %1;" : "=r"(r) : "f"(x));
    return r;
}
__device__ __forceinline__ float rnd_tf32(float x)
{
    return __uint_as_float(f2tf(x));
}

#define LDSM4(d, addr)                                                          \
    asm volatile("ldmatrix.sync.aligned.m8n8.x4.shared.b16 {%0,%1,%2,%3}, [%4];"\
                 : "=r"((d)[0]), "=r"((d)[1]), "=r"((d)[2]), "=r"((d)[3])       \
                 : "r"(addr))

#define MMA_TF32(c, a, b0v, b1v)                                                \
    asm volatile("mma.sync.aligned.m16n8k8.row.col.f32.tf32.tf32.f32 "          \
                 "{%0,%1,%2,%3}, {%4,%5,%6,%7}, {%8,%9}, {%0,%1,%2,%3};"        \
                 : "+f"((c)[0]), "+f"((c)[1]), "+f"((c)[2]), "+f"((c)[3])       \
                 : "r"((a)[0]), "r"((a)[1]), "r"((a)[2]), "r"((a)[3]),          \
                   "r"(b0v), "r"(b1v))

// ---------------- weight rounding (single fused launch) -------------------
__global__ void round_all(const float* __restrict__ s0, const float* __restrict__ s1,
                          const float* __restrict__ s2, const float* __restrict__ s3)
{
    int i4 = blockIdx.x * 256 + threadIdx.x;       // float4 index
    const float4* sp;
    if      (i4 < OFF_OUTW / 4) sp = (const float4*)s0 + i4;
    else if (i4 < OFF_W1 / 4)   sp = (const float4*)s1 + (i4 - OFF_OUTW / 4);
    else if (i4 < OFF_W2 / 4)   sp = (const float4*)s2 + (i4 - OFF_W1 / 4);
    else                        sp = (const float4*)s3 + (i4 - OFF_W2 / 4);
    float4 v = *sp;
    v.x = rnd_tf32(v.x); v.y = rnd_tf32(v.y);
    v.z = rnd_tf32(v.z); v.w = rnd_tf32(v.w);
    ((float4*)g_wr)[i4] = v;
}

// ---------------- x + pos (broadcast quirk: pos[0, b, :]) -----------------
__global__ void add_pos_kernel(const float* __restrict__ x,
                               const float* __restrict__ pos)
{
    int idx = blockIdx.x * 256 + threadIdx.x;
    int e4 = idx & (EMB / 4 - 1);
    int b  = (idx >> 7) & (BAT - 1);
    float4 xv = ((const float4*)x)[idx];
    float4 pv = ((const float4*)pos)[b * (EMB / 4) + e4];
    xv.x += pv.x; xv.y += pv.y; xv.z += pv.z; xv.w += pv.w;
    ((float4*)g_xp)[idx] = xv;
    float4 rv;
    rv.x = rnd_tf32(xv.x); rv.y = rnd_tf32(xv.y);
    rv.z = rnd_tf32(xv.z); rv.w = rnd_tf32(xv.w);
    ((float4*)g_xpr)[idx] = rv;
}

// ---------------- TF32 tensor-core GEMM (ldmatrix fragments) --------------
#define LDS 20
#define NSTAGE 4
#define STG_SZ (128 * LDS)
#define GEMM_SMEM (NSTAGE * 2 * STG_SZ * 4)

__global__ void __launch_bounds__(256, 2) gemm_tf32(
    const float* __restrict__ A, const float* __restrict__ Bw,
    const float* __restrict__ bias, float* __restrict__ C,
    int M, int N, int K, int mode)
{
    extern __shared__ float gsm[];
    float* Asm = gsm;
    float* Bsm = gsm + NSTAGE * STG_SZ;

    const int tid  = threadIdx.x;
    const int warp = tid >> 5, lane = tid & 31;
    const int wm = warp & 3, wn = warp >> 2;
    const int l4 = lane >> 2, lq = lane & 3;
    const int m0 = blockIdx.y * 128, n0 = blockIdx.x * 128;

    float acc[2][8][4];
    #pragma unroll
    for (int a = 0; a < 2; a++)
        #pragma unroll
        for (int b = 0; b < 8; b++)
            #pragma unroll
            for (int c = 0; c < 4; c++) acc[a][b][c] = 0.0f;

    const int g8 = lane >> 3, r8 = lane & 7;
    uint32_t a_off[2], b_off[4];
    #pragma unroll
    for (int mt = 0; mt < 2; mt++)
        a_off[mt] = ((wm * 32 + mt * 16 + (g8 & 1) * 8 + r8) * LDS
                     + (g8 >> 1) * 4) * 4;
    #pragma unroll
    for (int nt2 = 0; nt2 < 4; nt2++)
        b_off[nt2] = ((wn * 64 + nt2 * 16 + (g8 >> 1) * 8 + r8) * LDS
                      + (g8 & 1) * 4) * 4;
    const uint32_t smA = (uint32_t)__cvta_generic_to_shared(Asm);
    const uint32_t smB = (uint32_t)__cvta_generic_to_shared(Bsm);

    const int srow = tid >> 2, sc4 = (tid & 3) * 4;

    #define STAGE(s, k0)                                                        \
    {                                                                           \
        float* asb = Asm + (s) * STG_SZ;                                        \
        float* bsb = Bsm + (s) * STG_SZ;                                        \
        _Pragma("unroll")                                                       \
        for (int u = 0; u < 2; u++) {                                           \
            int row = srow + u * 64;                                            \
            const float* srcA = A + (size_t)(m0 + row) * K + (k0) + sc4;        \
            uint32_t dstA = (uint32_t)__cvta_generic_to_shared(                 \
                                &asb[row * LDS + sc4]);                         \
            asm volatile("cp.async.cg.shared.global [%0], [%1], 16;"            \
                         :: "r"(dstA), "l"(srcA));                              \
            const float* srcB = Bw + (size_t)(n0 + row) * K + (k0) + sc4;       \
            uint32_t dstB = (uint32_t)__cvta_generic_to_shared(                 \
                                &bsb[row * LDS + sc4]);                         \
            asm volatile("cp.async.cg.shared.global [%0], [%1], 16;"            \
                         :: "r"(dstB), "l"(srcB));                              \
        }                                                                       \
        asm volatile("cp.async.commit_group;");                                 \
    }

    const int nk = K >> 4;
    STAGE(0, 0);
    STAGE(1, 16);

    int buf = 0;
    for (int kt = 0; kt < nk; kt++) {
        if (kt + 1 < nk) asm volatile("cp.async.wait_group 1;");
        else             asm volatile("cp.async.wait_group 0;");
        __syncthreads();
        if (kt + 2 < nk) {
            int nb = buf + 2; if (nb >= NSTAGE) nb -= NSTAGE;
            STAGE(nb, (kt + 2) * 16);
        }
        const uint32_t baseA = smA + buf * (STG_SZ * 4);
        const uint32_t baseB = smB + buf * (STG_SZ * 4);
        #pragma unroll
        for (int ks = 0; ks < 16; ks += 8) {
            uint32_t af[2][4], bf4[4][4];
            #pragma unroll
            for (int mt = 0; mt < 2; mt++)
                LDSM4(af[mt], baseA + a_off[mt] + ks * 4);
            #pragma unroll
            for (int nt2 = 0; nt2 < 4; nt2++)
                LDSM4(bf4[nt2], baseB + b_off[nt2] + ks * 4);
            #pragma unroll
            for (int mt = 0; mt < 2; mt++)
                #pragma unroll
                for (int nt = 0; nt < 8; nt++)
                    MMA_TF32(acc[mt][nt], af[mt],
                             bf4[nt >> 1][(nt & 1) * 2],
                             bf4[nt >> 1][(nt & 1) * 2 + 1]);
        }
        buf++; if (buf >= NSTAGE) buf = 0;
    }
    __syncthreads();

    #pragma unroll
    for (int mt = 0; mt < 2; mt++) {
        int row = m0 + wm * 32 + mt * 16 + l4;
        #pragma unroll
        for (int nt = 0; nt < 8; nt++) {
            int col = n0 + wn * 64 + nt * 8 + lq * 2;
            float b0 = bias[col], b1 = bias[col + 1];
            float v0 = acc[mt][nt][0] + b0, v1 = acc[mt][nt][1] + b1;
            float v2 = acc[mt][nt][2] + b0, v3 = acc[mt][nt][3] + b1;
            if (mode == 1) {
                v0 = rnd_tf32(fmaxf(v0, 0.0f)); v1 = rnd_tf32(fmaxf(v1, 0.0f));
                v2 = rnd_tf32(fmaxf(v2, 0.0f)); v3 = rnd_tf32(fmaxf(v3, 0.0f));
            }
            *(float2*)&C[(size_t)row * N + col]       = make_float2(v0, v1);
            *(float2*)&C[(size_t)(row + 8) * N + col] = make_float2(v2, v3);
        }
    }
}

// ---------------- tiled sparse attention (flash-style, tf32 mma) ----------
// 256 threads = 8 warps per (64-query tile, b, h).
// QK^T and PV on tensor cores; softmax in fp32 on staged S.
#define QT 64
#define SPAD 68
#define ATTN_SMEM (4 * QT * SPAD * 4)

__global__ void __launch_bounds__(256) attn_tile_kernel()
{
    extern __shared__ float sm[];
    float* qs  = sm;                     // Q [64][SPAD] (scaled, rounded)
    float* kp  = sm + QT * SPAD;         // K chunk, then P
    float* vsT = sm + 2 * QT * SPAD;     // V^T [d][key]
    float* ss  = sm + 3 * QT * SPAD;     // staged scores S
    __shared__ float sm_sc[QT];          // per-row flash rescale
    __shared__ float sm_l[QT];           // per-row final sum

    const int q0  = blockIdx.x * QT;
    const int b   = blockIdx.y >> 3;
    const int h   = blockIdx.y & 7;
    const int tid = threadIdx.x;
    const int warp = tid >> 5, lane = tid & 31;
    const int wm = warp >> 1, wn = warp & 1;     // 4 x 2 warp grid
    const int l4 = lane >> 2, lq = lane & 3;
    const int g8 = lane >> 3, r8 = lane & 7;
    const int rt = tid >> 4, ct = tid & 15;      // softmax thread layout

    // ldmatrix byte offsets (row stride SPAD floats)
    const uint32_t aoff = ((wm * 16 + (g8 & 1) * 8 + r8) * SPAD + (g8 >> 1) * 4) * 4;
    uint32_t boff[2];
    #pragma unroll
    for (int nt2 = 0; nt2 < 2; nt2++)
        boff[nt2] = ((wn * 32 + nt2 * 16 + (g8 >> 1) * 8 + r8) * SPAD
                     + (g8 & 1) * 4) * 4;
    const uint32_t smbase = (uint32_t)__cvta_generic_to_shared(sm);
    const uint32_t qs_b = smbase;
    const uint32_t kp_b = smbase + QT * SPAD * 4;
    const uint32_t vs_b = smbase + 2 * QT * SPAD * 4;

    // load Q tile: scale + round
    #pragma unroll
    for (int u = 0; u < 4; u++) {
        int idx = tid + u * 256;
        int r = idx >> 4, c4 = idx & 15;
        float4 v = *(const float4*)&g_qkv[((size_t)(q0 + r) * BAT + b) * QKVE + h * HD + c4 * 4];
        v.x = rnd_tf32(v.x * 0.125f); v.y = rnd_tf32(v.y * 0.125f);
        v.z = rnd_tf32(v.z * 0.125f); v.w = rnd_tf32(v.w * 0.125f);
        *(float4*)&qs[r * SPAD + c4 * 4] = v;
    }

    float m[4], l[4];                    // softmax state (rt rows, replicated)
    #pragma unroll
    for (int rr = 0; rr < 4; rr++) { m[rr] = -1e30f; l[rr] = 0.0f; }
    float oa[4][4];                      // PV accumulators (mma frags)
    #pragma unroll
    for (int nt = 0; nt < 4; nt++)
        #pragma unroll
        for (int c = 0; c < 4; c++) oa[nt][c] = 0.0f;

    const int cov_lo = (q0 - WIN < 0) ? 0 : q0 - WIN;
    const int cov_hi = (q0 + QT + WIN > SEQ) ? SEQ : q0 + QT + WIN;
    const int nwchunk = (cov_hi - cov_lo) / QT;

    for (int cix = 0; cix <= nwchunk; cix++) {
        const bool is_glob = (cix == nwchunk);
        const int j0 = cov_lo + cix * QT;
        __syncthreads();                 // prev PV done with kp/vsT

        // ---- load K (rounded) and V (transposed, rounded) ----
        if (!is_glob) {
            #pragma unroll
            for (int u = 0; u < 4; u++) {
                int idx = tid + u * 256;
                int r = idx >> 4, c4 = idx & 15;
                size_t base = ((size_t)(j0 + r) * BAT + b) * QKVE + h * HD + c4 * 4;
                float4 kv = *(const float4*)&g_qkv[base + EMB];
                kv.x = rnd_tf32(kv.x); kv.y = rnd_tf32(kv.y);
                kv.z = rnd_tf32(kv.z); kv.w = rnd_tf32(kv.w);
                *(float4*)&kp[r * SPAD + c4 * 4] = kv;
                float4 vv = *(const float4*)&g_qkv[base + 2 * EMB];
                vsT[(c4 * 4 + 0) * SPAD + r] = rnd_tf32(vv.x);
                vsT[(c4 * 4 + 1) * SPAD + r] = rnd_tf32(vv.y);
                vsT[(c4 * 4 + 2) * SPAD + r] = rnd_tf32(vv.z);
                vsT[(c4 * 4 + 3) * SPAD + r] = rnd_tf32(vv.w);
            }
        } else if (tid < 128) {
            int r = tid >> 4, c4 = tid & 15;     // 8 global key rows
            size_t base = ((size_t)(r * 256) * BAT + b) * QKVE + h * HD + c4 * 4;
            float4 kv = *(const float4*)&g_qkv[base + EMB];
            kv.x = rnd_tf32(kv.x); kv.y = rnd_tf32(kv.y);
            kv.z = rnd_tf32(kv.z); kv.w = rnd_tf32(kv.w);
            *(float4*)&kp[r * SPAD + c4 * 4] = kv;
            float4 vv = *(const float4*)&g_qkv[base + 2 * EMB];
            vsT[(c4 * 4 + 0) * SPAD + r] = rnd_tf32(vv.x);
            vsT[(c4 * 4 + 1) * SPAD + r] = rnd_tf32(vv.y);
            vsT[(c4 * 4 + 2) * SPAD + r] = rnd_tf32(vv.z);
            vsT[(c4 * 4 + 3) * SPAD + r] = rnd_tf32(vv.w);
        }
        __syncthreads();

        // ---- QK^T mma: S = Q @ K^T (contraction over HD=64) ----
        {
            const int ntmax = is_glob ? 1 : 4;
            if (!(is_glob && wn == 1)) {
                float sacc[4][4];
                #pragma unroll
                for (int nt = 0; nt < 4; nt++)
                    #pragma unroll
                    for (int c = 0; c < 4; c++) sacc[nt][c] = 0.0f;
                #pragma unroll
                for (int k8 = 0; k8 < 8; k8++) {
                    uint32_t af[4], bf0[4], bf1[4];
                    LDSM4(af,  qs_b + aoff + k8 * 32);
                    LDSM4(bf0, kp_b + boff[0] + k8 * 32);
                    LDSM4(bf1, kp_b + boff[1] + k8 * 32);
                    for (int nt = 0; nt < ntmax; nt++) {
                        const uint32_t* bb = (nt >> 1) ? bf1 : bf0;
                        MMA_TF32(sacc[nt], af, bb[(nt & 1) * 2], bb[(nt & 1) * 2 + 1]);
                    }
                }
                // stage S to smem
                const int row = wm * 16 + l4;
                for (int nt = 0; nt < ntmax; nt++) {
                    const int col = wn * 32 + nt * 8 + lq * 2;
                    *(float2*)&ss[row * SPAD + col] =
                        make_float2(sacc[nt][0], sacc[nt][1]);
                    *(float2*)&ss[(row + 8) * SPAD + col] =
                        make_float2(sacc[nt][2], sacc[nt][3]);
                }
            }
        }
        __syncthreads();

        // ---- softmax on staged S (rt/ct layout, as validated) ----
        {
            float s[4][4];
            float mc[4];
            #pragma unroll
            for (int rr = 0; rr < 4; rr++) {
                const int i = q0 + rt * 4 + rr;
                float mm = -1e30f;
                #pragma unroll
                for (int cc = 0; cc < 4; cc++) {
                    const int c = ct * 4 + cc;
                    float sv = ss[(rt * 4 + rr) * SPAD + c];
                    bool ok;
                    if (is_glob) {
                        const int j = c * 256;
                        ok = (c < 8) && (j < cov_lo || j >= cov_hi);
                    } else {
                        const int j = j0 + c;
                        const int d = i - j;
                        ok = (d <= WIN && d >= -WIN) || ((j & 255) == 0);
                    }
                    s[rr][cc] = ok ? sv : -1e30f;
                    mm = fmaxf(mm, s[rr][cc]);
                }
                mc[rr] = mm;
            }
            #pragma unroll
            for (int off = 1; off < 16; off <<= 1)
                #pragma unroll
                for (int rr = 0; rr < 4; rr++)
                    mc[rr] = fmaxf(mc[rr], __shfl_xor_sync(~0u, mc[rr], off));

            float psum[4];
            #pragma unroll
            for (int rr = 0; rr < 4; rr++) {
                float mn = fmaxf(m[rr], mc[rr]);
                float scale = __expf(m[rr] - mn);
                m[rr] = mn;
                l[rr] *= scale;
                if (ct == 0) sm_sc[rt * 4 + rr] = scale;
                float ps = 0.0f;
                #pragma unroll
                for (int cc = 0; cc < 4; cc++) {
                    float p = (s[rr][cc] > -1e29f) ? __expf(s[rr][cc] - mn) : 0.0f;
                    s[rr][cc] = p;
                    ps += p;
                }
                psum[rr] = ps;
            }
            #pragma unroll
            for (int off = 1; off < 16; off <<= 1)
                #pragma unroll
                for (int rr = 0; rr < 4; rr++)
                    psum[rr] += __shfl_xor_sync(~0u, psum[rr], off);
            #pragma unroll
            for (int rr = 0; rr < 4; rr++) l[rr] += psum[rr];

            // stage P (rounded) into kp — K is dead now
            #pragma unroll
            for (int rr = 0; rr < 4; rr++)
                *(float4*)&kp[(rt * 4 + rr) * SPAD + ct * 4] =
                    make_float4(rnd_tf32(s[rr][0]), rnd_tf32(s[rr][1]),
                                rnd_tf32(s[rr][2]), rnd_tf32(s[rr][3]));
        }
        __syncthreads();

        // ---- PV mma: O += P @ V  (contraction over keys) ----
        {
            const float sc0 = sm_sc[wm * 16 + l4];
            const float sc1 = sm_sc[wm * 16 + l4 + 8];
            #pragma unroll
            for (int nt = 0; nt < 4; nt++) {
                oa[nt][0] *= sc0; oa[nt][1] *= sc0;
                oa[nt][2] *= sc1; oa[nt][3] *= sc1;
            }
            const int kmax = is_glob ? 1 : 8;
            for (int k8 = 0; k8 < kmax; k8++) {
                uint32_t af[4], bf0[4], bf1[4];
                LDSM4(af,  kp_b + aoff + k8 * 32);          // P rows (q)
                LDSM4(bf0, vs_b + boff[0] + k8 * 32);       // V^T rows (d)
                LDSM4(bf1, vs_b + boff[1] + k8 * 32);
                #pragma unroll
                for (int nt = 0; nt < 4; nt++) {
                    const uint32_t* bb = (nt >> 1) ? bf1 : bf0;
                    MMA_TF32(oa[nt], af, bb[(nt & 1) * 2], bb[(nt & 1) * 2 + 1]);
                }
            }
        }
    }

    // final per-row sums -> smem, then normalize + write
    if (ct == 0)
        #pragma unroll
        for (int rr = 0; rr < 4; rr++) sm_l[rt * 4 + rr] = l[rr];
    __syncthreads();

    {
        const int row0 = wm * 16 + l4;
        const float inv0 = 1.0f / sm_l[row0];
        const float inv1 = 1.0f / sm_l[row0 + 8];
        #pragma unroll
        for (int nt = 0; nt < 4; nt++) {
            const int col = wn * 32 + nt * 8 + lq * 2;
            size_t base0 = ((size_t)(q0 + row0) * BAT + b) * EMB + h * HD + col;
            size_t base1 = ((size_t)(q0 + row0 + 8) * BAT + b) * EMB + h * HD + col;
            *(float2*)&g_y[base0] =
                make_float2(rnd_tf32(oa[nt][0] * inv0), rnd_tf32(oa[nt][1] * inv0));
            *(float2*)&g_y[base1] =
                make_float2(rnd_tf32(oa[nt][2] * inv1), rnd_tf32(oa[nt][3] * inv1));
        }
    }
}

// ---------------- fused residual add + layernorm --------------------------
__global__ void add_ln_kernel(const float* __restrict__ a,
                              const float* __restrict__ r,
                              const float* __restrict__ g,
                              const float* __restrict__ be,
                              float* __restrict__ out,
                              float* __restrict__ out_r)
{
    const int row = blockIdx.x;
    const int tid = threadIdx.x;
    __shared__ float red[4];
    __shared__ float s_stat[2];

    float v[4];
    float s = 0.0f;
    #pragma unroll
    for (int u = 0; u < 4; u++) {
        int e = tid + u * 128;
        v[u] = a[(size_t)row * EMB + e] + r[(size_t)row * EMB + e];
        s += v[u];
    }
    #pragma unroll
    for (int o = 16; o; o >>= 1) s += __shfl_xor_sync(~0u, s, o);
    if ((tid & 31) == 0) red[tid >> 5] = s;
    __syncthreads();
    const float mean = (red[0] + red[1] + red[2] + red[3]) * (1.0f / EMB);
    __syncthreads();

    float s2 = 0.0f;
    #pragma unroll
    for (int u = 0; u < 4; u++) {
        float dl = v[u] - mean;
        s2 += dl * dl;
    }
    #pragma unroll
    for (int o = 16; o; o >>= 1) s2 += __shfl_xor_sync(~0u, s2, o);
    if ((tid & 31) == 0) red[tid >> 5] = s2;
    __syncthreads();
    if (tid == 0) s_stat[0] = (red[0] + red[1] + red[2] + red[3]) * (1.0f / EMB);
    __syncthreads();
    const float rstd = rsqrtf(s_stat[0] + 1e-5f);

    #pragma unroll
    for (int u = 0; u < 4; u++) {
        int e = tid + u * 128;
        float ov = (v[u] - mean) * rstd * g[e] + be[e];
        out[(size_t)row * EMB + e] = ov;
        if (out_r) out_r[(size_t)row * EMB + e] = rnd_tf32(ov);
    }
}

// ---------------- launch ---------------------------------------------------
extern "C" void kernel_launch(void* const* d_in, const int* in_sizes, int n_in,
                              void* d_out, int out_size)
{
    const float* x         = (const float*)d_in[0];
    const float* pos       = (const float*)d_in[1];
    const float* in_proj_w = (const float*)d_in[2];
    const float* in_proj_b = (const float*)d_in[3];
    const float* out_w     = (const float*)d_in[4];
    const float* out_b     = (const float*)d_in[5];
    const float* w1        = (const float*)d_in[6];
    const float* b1        = (const float*)d_in[7];
    const float* w2        = (const float*)d_in[8];
    const float* b2        = (const float*)d_in[9];
    const float* g1        = (const float*)d_in[10];
    const float* be1       = (const float*)d_in[11];
    const float* g2        = (const float*)d_in[12];
    const float* be2       = (const float*)d_in[13];
    float* out = (float*)d_out;

    float *xpr, *qkv, *y, *tmp, *ln1, *ln1r, *ffh, *wr, *xp;
    cudaGetSymbolAddress((void**)&xp,   g_xp);
    cudaGetSymbolAddress((void**)&xpr,  g_xpr);
    cudaGetSymbolAddress((void**)&qkv,  g_qkv);
    cudaGetSymbolAddress((void**)&y,    g_y);
    cudaGetSymbolAddress((void**)&tmp,  g_tmp);
    cudaGetSymbolAddress((void**)&ln1,  g_ln1);
    cudaGetSymbolAddress((void**)&ln1r, g_ln1r);
    cudaGetSymbolAddress((void**)&ffh,  g_ffh);
    cudaGetSymbolAddress((void**)&wr,   g_wr);

    cudaFuncSetAttribute(attn_tile_kernel,
                         cudaFuncAttributeMaxDynamicSharedMemorySize, ATTN_SMEM);
    cudaFuncSetAttribute(gemm_tf32,
                         cudaFuncAttributeMaxDynamicSharedMemorySize, GEMM_SMEM);

    // 0. round all weights to tf32 (one launch)
    round_all<<<(W_TOTAL / 4) / 256, 256>>>(in_proj_w, out_w, w1, w2);

    // 1. x + pos (full + rounded)
    add_pos_kernel<<<(TOK * EMB / 4) / 256, 256>>>(x, pos);

    // 2. QKV projection
    gemm_tf32<<<dim3(QKVE / 128, TOK / 128), 256, GEMM_SMEM>>>(
        xpr, wr + OFF_INPROJ, in_proj_b, qkv, TOK, QKVE, EMB, 0);

    // 3. tiled sparse attention (tensor-core)
    attn_tile_kernel<<<dim3(SEQ / QT, BAT * NH), 256, ATTN_SMEM>>>();

    // 4. out projection
    gemm_tf32<<<dim3(EMB / 128, TOK / 128), 256, GEMM_SMEM>>>(
        y, wr + OFF_OUTW, out_b, tmp, TOK, EMB, EMB, 0);

    // 5. residual + LN1 (full + rounded)
    add_ln_kernel<<<TOK, 128>>>(xp, tmp, g1, be1, ln1, ln1r);

    // 6. FF1 + ReLU (epilogue rounds)
    gemm_tf32<<<dim3(FFD / 128, TOK / 128), 256, GEMM_SMEM>>>(
        ln1r, wr + OFF_W1, b1, ffh, TOK, FFD, EMB, 1);

    // 7. FF2
    gemm_tf32<<<dim3(EMB / 128, TOK / 128), 256, GEMM_SMEM>>>(
        ffh, wr + OFF_W2, b2, tmp, TOK, EMB, FFD, 0);

    // 8. residual + LN2 -> output
    add_ln_kernel<<<TOK, 128>>>(ln1, tmp, g2, be2, out, nullptr);
}